// round 1
// baseline (speedup 1.0000x reference)
#include <cuda_runtime.h>
#include <cuda_bf16.h>

#define B_   16
#define L_   2048
#define H_   512
#define N_   64
#define C_   64
#define NCH  32   // L_/C_

// ---------------- scratch (__device__ globals; no runtime allocation) -------
__device__ float2 d_W  [H_ * C_ * N_];   // [h][j][n] : Ab^{C-1-j} * Bb
__device__ float2 d_M  [H_ * C_ * N_];   // [h][i][n] : Cc * Ab^{i+1}
__device__ float  d_Kt [H_ * C_];        // [h][d]    : Re(sum_n CB * Ab^d)
__device__ float2 d_AbC[H_ * N_];        // [h][n]    : Ab^C
__device__ float  d_ut [B_ * H_ * L_];   // u transposed (B,H,L)
__device__ float2 d_g  [B_ * H_ * NCH * N_];  // [b][h][c][n]
__device__ float2 d_xp [B_ * H_ * NCH * N_];  // state BEFORE chunk c
__device__ float  d_yt [B_ * H_ * L_];   // y transposed (B,H,L)

__device__ __forceinline__ float2 cmul(float2 a, float2 b) {
    return make_float2(a.x * b.x - a.y * b.y, a.x * b.y + a.y * b.x);
}

// ---------------- precompute: discretization + chunk operators --------------
__global__ void precompute_kernel(const float* __restrict__ Lr,
                                  const float* __restrict__ Li,
                                  const float* __restrict__ Br,
                                  const float* __restrict__ Bi,
                                  const float* __restrict__ Cr,
                                  const float* __restrict__ Ci,
                                  const float* __restrict__ logdt) {
    int h = blockIdx.x;
    int n = threadIdx.x;             // 64 threads

    float dt  = expf(logdt[h]);
    float lr  = Lr[n], li = Li[n];
    float dar = dt * lr, dai = dt * li;

    // Ab = exp(dt * Lambda)
    float er = expf(dar);
    float s, c;
    sincosf(dai, &s, &c);
    float2 Ab = make_float2(er * c, er * s);

    // Bb = Bc * (Ab - 1) / (Lambda + 1e-8)
    float dr = lr + 1e-8f, di = li;
    float inv = 1.0f / (dr * dr + di * di);
    float2 Am1 = make_float2(Ab.x - 1.0f, Ab.y);
    float2 Bc  = make_float2(Br[h * N_ + n], Bi[h * N_ + n]);
    float2 num = cmul(Bc, Am1);
    float2 Bb  = make_float2((num.x * dr + num.y * di) * inv,
                             (num.y * dr - num.x * di) * inv);
    float2 Cc  = make_float2(Cr[h * N_ + n], Ci[h * N_ + n]);
    float2 CB  = cmul(Cc, Bb);

    __shared__ float sK[C_][N_ + 1];

    float2 p = make_float2(1.0f, 0.0f);        // Ab^e
    #pragma unroll 4
    for (int e = 0; e < C_; e++) {
        d_W[(h * C_ + (C_ - 1 - e)) * N_ + n] = cmul(p, Bb);   // W[j=C-1-e]
        sK[e][n] = CB.x * p.x - CB.y * p.y;                    // Re(CB*Ab^e)
        p = cmul(p, Ab);                                       // Ab^{e+1}
        d_M[(h * C_ + e) * N_ + n] = cmul(Cc, p);              // M[i=e]
    }
    d_AbC[h * N_ + n] = p;                                     // Ab^C
    __syncthreads();

    // reduce over n: Ktop[h][d] (thread n handles d = n; C_ == N_)
    float acc = 0.0f;
    #pragma unroll 8
    for (int m = 0; m < N_; m++) acc += sK[n][m];
    d_Kt[h * C_ + n] = acc;
}

// ---------------- transposes -------------------------------------------------
__global__ void transpose_BLH_to_BHL(const float* __restrict__ in, float* __restrict__ out) {
    __shared__ float tile[32][33];
    int b = blockIdx.z;
    int h0 = blockIdx.x * 32, l0 = blockIdx.y * 32;
    int tx = threadIdx.x, ty = threadIdx.y;   // (32, 8)
    #pragma unroll
    for (int k = 0; k < 4; k++) {
        int l = l0 + ty + k * 8;
        tile[ty + k * 8][tx] = in[((size_t)b * L_ + l) * H_ + h0 + tx];
    }
    __syncthreads();
    #pragma unroll
    for (int k = 0; k < 4; k++) {
        int h = h0 + ty + k * 8;
        out[((size_t)b * H_ + h) * L_ + l0 + tx] = tile[tx][ty + k * 8];
    }
}

__global__ void transpose_BHL_to_BLH(const float* __restrict__ in, float* __restrict__ out) {
    __shared__ float tile[32][33];
    int b = blockIdx.z;
    int l0 = blockIdx.x * 32, h0 = blockIdx.y * 32;
    int tx = threadIdx.x, ty = threadIdx.y;
    #pragma unroll
    for (int k = 0; k < 4; k++) {
        int h = h0 + ty + k * 8;
        tile[ty + k * 8][tx] = in[((size_t)b * H_ + h) * L_ + l0 + tx];
    }
    __syncthreads();
    #pragma unroll
    for (int k = 0; k < 4; k++) {
        int l = l0 + ty + k * 8;
        out[((size_t)b * L_ + l) * H_ + h0 + tx] = tile[tx][ty + k * 8];
    }
}

// ---------------- per-chunk input projection: g = W @ u_chunk ---------------
__global__ void chunk_in_kernel() {
    int h = blockIdx.x;
    int b = blockIdx.y;
    __shared__ float2 Wsh[N_][C_ + 1];   // [n][j], padded
    __shared__ float  ush[L_];

    int tid = threadIdx.x;               // 256
    const float2* Wg = d_W + (size_t)h * C_ * N_;   // [j][n]
    for (int idx = tid; idx < C_ * N_; idx += 256) {
        int j = idx >> 6, n = idx & 63;
        Wsh[n][j] = Wg[idx];
    }
    const float* up = d_ut + ((size_t)b * H_ + h) * L_;
    for (int idx = tid; idx < L_; idx += 256) ush[idx] = up[idx];
    __syncthreads();

    int n  = tid & 63;
    int c4 = tid >> 6;
    float2* gp = d_g + ((size_t)(b * H_ + h) * NCH) * N_;
    #pragma unroll
    for (int cc = 0; cc < 8; cc++) {
        int c = cc * 4 + c4;
        const float* ub = ush + c * C_;
        float sr = 0.0f, si = 0.0f;
        #pragma unroll
        for (int j = 0; j < C_; j++) {
            float  uj = ub[j];
            float2 w  = Wsh[n][j];
            sr += w.x * uj;
            si += w.y * uj;
        }
        gp[c * N_ + n] = make_float2(sr, si);
    }
}

// ---------------- sequential scan over chunks --------------------------------
__global__ void scan_kernel() {
    int idx = blockIdx.x * 256 + threadIdx.x;   // B*H*N threads
    int n = idx & 63;
    int h = (idx >> 6) & (H_ - 1);
    int b = idx >> 15;
    float2 a = d_AbC[h * N_ + n];
    float2 x = make_float2(0.0f, 0.0f);
    size_t base = ((size_t)(b * H_ + h) * NCH) * N_ + n;
    #pragma unroll 4
    for (int c = 0; c < NCH; c++) {
        d_xp[base + (size_t)c * N_] = x;
        float2 g = d_g[base + (size_t)c * N_];
        x = make_float2(a.x * x.x - a.y * x.y + g.x,
                        a.x * x.y + a.y * x.x + g.y);
    }
}

// ---------------- output: inter (M @ x) + intra Toeplitz + skip --------------
extern __shared__ float smem_raw[];
__global__ void out_kernel(const float* __restrict__ Din) {
    int h = blockIdx.x;
    int b = blockIdx.y;
    float2* Msh = (float2*)smem_raw;          // [n][i]  64*64
    float2* xsh = Msh + N_ * C_;              // [c][n]  32*64
    float*  Ksh = (float*)(xsh + NCH * N_);   // 64
    float*  ush = Ksh + C_;                   // 2048

    int tid = threadIdx.x;   // 256
    const float2* Mg = d_M + (size_t)h * C_ * N_;   // [i][n]
    for (int idx = tid; idx < C_ * N_; idx += 256) {
        int i = idx >> 6, n = idx & 63;
        Msh[n * C_ + i] = Mg[idx];
    }
    const float2* xg = d_xp + ((size_t)(b * H_ + h) * NCH) * N_;
    for (int idx = tid; idx < NCH * N_; idx += 256) xsh[idx] = xg[idx];
    if (tid < C_) Ksh[tid] = d_Kt[h * C_ + tid];
    const float* up = d_ut + ((size_t)b * H_ + h) * L_;
    for (int idx = tid; idx < L_; idx += 256) ush[idx] = up[idx];
    __syncthreads();

    float Dh = Din[h];
    float* yp = d_yt + ((size_t)b * H_ + h) * L_;
    #pragma unroll
    for (int rep = 0; rep < 8; rep++) {
        int l = rep * 256 + tid;
        int c = l >> 6, i = l & 63;
        float acc = Dh * ush[l];
        const float2* xc = xsh + c * N_;
        #pragma unroll
        for (int n = 0; n < N_; n++) {
            float2 m  = Msh[n * C_ + i];
            float2 xv = xc[n];
            acc += m.x * xv.x - m.y * xv.y;   // Re(M * x)
        }
        const float* ub = ush + c * C_;
        for (int j = 0; j <= i; j++) acc += Ksh[i - j] * ub[j];
        yp[l] = acc;
    }
}

// ---------------- launch ------------------------------------------------------
extern "C" void kernel_launch(void* const* d_in, const int* in_sizes, int n_in,
                              void* d_out, int out_size) {
    const float* u     = (const float*)d_in[0];
    const float* Lr    = (const float*)d_in[1];
    const float* Li    = (const float*)d_in[2];
    const float* Br    = (const float*)d_in[3];
    const float* Bi    = (const float*)d_in[4];
    const float* Cr    = (const float*)d_in[5];
    const float* Ci    = (const float*)d_in[6];
    const float* logdt = (const float*)d_in[7];
    const float* D     = (const float*)d_in[8];
    float* out = (float*)d_out;

    float* ut_ptr; cudaGetSymbolAddress((void**)&ut_ptr, d_ut);
    float* yt_ptr; cudaGetSymbolAddress((void**)&yt_ptr, d_yt);

    static const int OUT_SMEM = (N_ * C_ + NCH * N_) * 8 + C_ * 4 + L_ * 4;  // 57600
    cudaFuncSetAttribute(out_kernel, cudaFuncAttributeMaxDynamicSharedMemorySize, OUT_SMEM);

    precompute_kernel<<<H_, N_>>>(Lr, Li, Br, Bi, Cr, Ci, logdt);
    transpose_BLH_to_BHL<<<dim3(H_ / 32, L_ / 32, B_), dim3(32, 8)>>>(u, ut_ptr);
    chunk_in_kernel<<<dim3(H_, B_), 256>>>();
    scan_kernel<<<(B_ * H_ * N_) / 256, 256>>>();
    out_kernel<<<dim3(H_, B_), 256, OUT_SMEM>>>(D);
    transpose_BHL_to_BLH<<<dim3(L_ / 32, H_ / 32, B_), dim3(32, 8)>>>(yt_ptr, out);
}

// round 2
// speedup vs baseline: 2.6602x; 2.6602x over previous
#include <cuda_runtime.h>
#include <cuda_bf16.h>
#include <cstdint>

#define B_   16
#define L_   2048
#define H_   512
#define N_   64
#define C_   64
#define NCH  32   // L_/C_

#define WROW 68                   // padded W row (floats): conflict-free LDS.128
// fused-kernel dynamic smem layout (float offsets)
#define oWr  0
#define oWi  4352                 // 64*68
#define oA2  8704                 // + 64*68      (A2: float2 [96][64] = 12288 floats)
#define oU   20992                // + 96*64*2
#define oXR  23040                // + 2048
#define oXI  25088                // + 32*64
#define FTOT 27136                // + 32*64  -> 108544 bytes

// ---------------- scratch (__device__ globals) -------------------------------
__device__ __align__(16) float  d_Wr [H_ * N_ * WROW];   // [h][n][j] Re(Ab^{63-j} Bb)
__device__ __align__(16) float  d_Wi [H_ * N_ * WROW];
__device__ __align__(16) float2 d_A2p[H_ * 96 * 64];     // [h][kp][i] = (A2[2kp][i], A2[2kp+1][i])
__device__ __align__(16) float2 d_AbC[H_ * N_];          // Ab^C
__device__ __align__(16) float  d_ut [B_ * H_ * L_];     // u transposed (B,H,L)
__device__ __align__(16) float  d_yt [B_ * H_ * L_];     // y transposed (B,H,L)

__device__ __forceinline__ float2 cmul(float2 a, float2 b) {
    return make_float2(a.x * b.x - a.y * b.y, a.x * b.y + a.y * b.x);
}

// packed f32x2 helpers --------------------------------------------------------
__device__ __forceinline__ unsigned long long lds_b64(uint32_t a) {
    unsigned long long v;
    asm volatile("ld.shared.b64 %0, [%1];" : "=l"(v) : "r"(a));
    return v;
}
__device__ __forceinline__ void lds_v2b64(uint32_t a, unsigned long long& x, unsigned long long& y) {
    asm volatile("ld.shared.v2.u64 {%0,%1}, [%2];" : "=l"(x), "=l"(y) : "r"(a));
}
__device__ __forceinline__ unsigned long long fma2(unsigned long long a, unsigned long long b,
                                                   unsigned long long c) {
    unsigned long long d;
    asm("fma.rn.f32x2 %0, %1, %2, %3;" : "=l"(d) : "l"(a), "l"(b), "l"(c));
    return d;
}
__device__ __forceinline__ float hsum2(unsigned long long v) {
    float lo, hi;
    asm("mov.b64 {%0,%1}, %2;" : "=f"(lo), "=f"(hi) : "l"(v));
    return lo + hi;
}

// ---------------- precompute: discretization + packed operators --------------
__global__ void precompute_kernel(const float* __restrict__ Lr,
                                  const float* __restrict__ Li,
                                  const float* __restrict__ Br,
                                  const float* __restrict__ Bi,
                                  const float* __restrict__ Cr,
                                  const float* __restrict__ Ci,
                                  const float* __restrict__ logdt) {
    int h = blockIdx.x;
    int n = threadIdx.x;             // 64 threads
    int lane = n & 31, wid = n >> 5;

    float dt  = expf(logdt[h]);
    float lr  = Lr[n], li = Li[n];
    float er = expf(dt * lr);
    float s, c;
    sincosf(dt * li, &s, &c);
    float2 Ab = make_float2(er * c, er * s);

    // Bb = Bc*(Ab-1)/(Lambda+1e-8)
    float dr = lr + 1e-8f, di = li;
    float inv = 1.0f / (dr * dr + di * di);
    float2 Am1 = make_float2(Ab.x - 1.0f, Ab.y);
    float2 Bc  = make_float2(Br[h * N_ + n], Bi[h * N_ + n]);
    float2 num = cmul(Bc, Am1);
    float2 Bb  = make_float2((num.x * dr + num.y * di) * inv,
                             (num.y * dr - num.x * di) * inv);
    float2 Cc  = make_float2(Cr[h * N_ + n], Ci[h * N_ + n]);
    float2 CB  = cmul(Cc, Bb);

    __shared__ float sMr[64][65], sMi[64][65];
    __shared__ float sKpart[64][2];
    __shared__ float sKd[64];

    float* wrow_r = d_Wr + (size_t)h * N_ * WROW + n * WROW;
    float* wrow_i = d_Wi + (size_t)h * N_ * WROW + n * WROW;

    float2 p = make_float2(1.0f, 0.0f);              // Ab^e
    for (int e = 0; e < C_; e++) {
        float2 w = cmul(p, Bb);                      // Ab^e * Bb  (j = 63-e)
        wrow_r[63 - e] = w.x;
        wrow_i[63 - e] = w.y;
        float kv = CB.x * p.x - CB.y * p.y;          // Re(CB * Ab^e)
        #pragma unroll
        for (int off = 16; off; off >>= 1) kv += __shfl_xor_sync(0xffffffffu, kv, off);
        if (lane == 0) sKpart[e][wid] = kv;
        p = cmul(p, Ab);                             // Ab^{e+1}
        float2 m = cmul(Cc, p);
        sMr[e][n] = m.x;
        sMi[e][n] = m.y;
    }
    d_AbC[h * N_ + n] = p;                           // Ab^C
    __syncthreads();
    sKd[n] = sKpart[n][0] + sKpart[n][1];            // K[d=n]
    __syncthreads();

    // pack A2p[kp][i]: thread handles row i = n
    float2* A2g = d_A2p + (size_t)h * 96 * 64;
    #pragma unroll 4
    for (int kp = 0; kp < 32; kp++)                  // k in [0,64): Mr, times xr
        A2g[kp * 64 + n] = make_float2(sMr[n][2 * kp], sMr[n][2 * kp + 1]);
    #pragma unroll 4
    for (int kp = 32; kp < 64; kp++)                 // k in [64,128): -Mi, times xi
        A2g[kp * 64 + n] = make_float2(-sMi[n][2 * kp - 64], -sMi[n][2 * kp - 63]);
    #pragma unroll 4
    for (int kp = 64; kp < 96; kp++) {               // k in [128,192): Toeplitz K, times u
        int j0 = 2 * (kp - 64);
        float v0 = (n >= j0)     ? sKd[n - j0]     : 0.0f;
        float v1 = (n >= j0 + 1) ? sKd[n - j0 - 1] : 0.0f;
        A2g[kp * 64 + n] = make_float2(v0, v1);
    }
}

// ---------------- transposes --------------------------------------------------
__global__ void transpose_BLH_to_BHL(const float* __restrict__ in, float* __restrict__ out) {
    __shared__ float tile[32][33];
    int b = blockIdx.z;
    int h0 = blockIdx.x * 32, l0 = blockIdx.y * 32;
    int tx = threadIdx.x, ty = threadIdx.y;   // (32, 8)
    #pragma unroll
    for (int k = 0; k < 4; k++) {
        int l = l0 + ty + k * 8;
        tile[ty + k * 8][tx] = in[((size_t)b * L_ + l) * H_ + h0 + tx];
    }
    __syncthreads();
    #pragma unroll
    for (int k = 0; k < 4; k++) {
        int h = h0 + ty + k * 8;
        out[((size_t)b * H_ + h) * L_ + l0 + tx] = tile[tx][ty + k * 8];
    }
}

__global__ void transpose_BHL_to_BLH(const float* __restrict__ in, float* __restrict__ out) {
    __shared__ float tile[32][33];
    int b = blockIdx.z;
    int l0 = blockIdx.x * 32, h0 = blockIdx.y * 32;
    int tx = threadIdx.x, ty = threadIdx.y;
    #pragma unroll
    for (int k = 0; k < 4; k++) {
        int h = h0 + ty + k * 8;
        tile[ty + k * 8][tx] = in[((size_t)b * H_ + h) * L_ + l0 + tx];
    }
    __syncthreads();
    #pragma unroll
    for (int k = 0; k < 4; k++) {
        int l = l0 + ty + k * 8;
        out[((size_t)b * L_ + l) * H_ + h0 + tx] = tile[tx][ty + k * 8];
    }
}

// ---------------- fused: projection + scan + output per (b,h) ----------------
extern __shared__ float fsm[];
__global__ __launch_bounds__(256) void fused_kernel(const float* __restrict__ Din) {
    int b = blockIdx.x;
    int h = blockIdx.y;
    int tid = threadIdx.x;

    // ---- stage operators + u into smem
    {
        const float4* src = (const float4*)(d_Wr + (size_t)h * N_ * WROW);
        float4* dst = (float4*)(fsm + oWr);
        for (int i = tid; i < (N_ * WROW) / 4; i += 256) dst[i] = src[i];
    }
    {
        const float4* src = (const float4*)(d_Wi + (size_t)h * N_ * WROW);
        float4* dst = (float4*)(fsm + oWi);
        for (int i = tid; i < (N_ * WROW) / 4; i += 256) dst[i] = src[i];
    }
    {
        const float4* src = (const float4*)(d_A2p + (size_t)h * 96 * 64);
        float4* dst = (float4*)(fsm + oA2);
        for (int i = tid; i < (96 * 64 * 2) / 4; i += 256) dst[i] = src[i];
    }
    {
        const float4* src = (const float4*)(d_ut + ((size_t)b * H_ + h) * L_);
        float4* dst = (float4*)(fsm + oU);
        for (int i = tid; i < L_ / 4; i += 256) dst[i] = src[i];
    }
    __syncthreads();

    // ---- phase 1: g[c][n] = sum_j W[j][n] * u[c*64+j]  (complex)
    {
        int n  = tid & 63;
        int cg = tid >> 6;                       // 0..3
        float accr[8], acci[8];
        #pragma unroll
        for (int cc = 0; cc < 8; cc++) { accr[cc] = 0.0f; acci[cc] = 0.0f; }
        const float* wr = fsm + oWr + n * WROW;
        const float* wi = fsm + oWi + n * WROW;
        #pragma unroll 4
        for (int jq = 0; jq < 16; jq++) {
            float4 w4r = *(const float4*)(wr + jq * 4);
            float4 w4i = *(const float4*)(wi + jq * 4);
            #pragma unroll
            for (int cc = 0; cc < 8; cc++) {
                int c = cc * 4 + cg;
                float4 u4 = *(const float4*)(fsm + oU + c * 64 + jq * 4);
                accr[cc] += w4r.x * u4.x; accr[cc] += w4r.y * u4.y;
                accr[cc] += w4r.z * u4.z; accr[cc] += w4r.w * u4.w;
                acci[cc] += w4i.x * u4.x; acci[cc] += w4i.y * u4.y;
                acci[cc] += w4i.z * u4.z; acci[cc] += w4i.w * u4.w;
            }
        }
        #pragma unroll
        for (int cc = 0; cc < 8; cc++) {
            int c = cc * 4 + cg;
            fsm[oXR + c * 64 + n] = accr[cc];
            fsm[oXI + c * 64 + n] = acci[cc];
        }
    }
    __syncthreads();

    // ---- phase 2: sequential scan over chunks (in-place: g -> x-prefix)
    if (tid < 64) {
        float2 a = d_AbC[h * N_ + tid];
        float xr = 0.0f, xi = 0.0f;
        #pragma unroll 4
        for (int c = 0; c < NCH; c++) {
            float gr = fsm[oXR + c * 64 + tid];
            float gi = fsm[oXI + c * 64 + tid];
            fsm[oXR + c * 64 + tid] = xr;
            fsm[oXI + c * 64 + tid] = xi;
            float nxr = a.x * xr - a.y * xi + gr;
            xi = a.x * xi + a.y * xr + gi;
            xr = nxr;
        }
    }
    __syncthreads();

    // ---- phase 3: y[c][i] = A2(64x192) @ [xr;xi;u_chunk] + D*u   (f32x2 packed)
    {
        int i2  = tid & 31;                      // i pair: i = 2*i2, 2*i2+1
        int cg2 = tid >> 5;                      // 0..7
        unsigned long long acc[8];
        #pragma unroll
        for (int k = 0; k < 8; k++) acc[k] = 0ull;

        uint32_t sbase = (uint32_t)__cvta_generic_to_shared(fsm);
        uint32_t aAb = sbase + oA2 * 4 + i2 * 16;                     // + kp*512
        uint32_t xb0 = sbase + oXR * 4;
        uint32_t xb1 = sbase + oXI * 4;
        uint32_t xb2 = sbase + oU  * 4;

        #pragma unroll 1
        for (int seg = 0; seg < 3; seg++) {
            uint32_t xb = (seg == 0) ? xb0 : (seg == 1) ? xb1 : xb2;
            uint32_t aA = aAb + seg * 32 * 512;
            #pragma unroll 4
            for (int kpl = 0; kpl < 32; kpl++) {
                unsigned long long pa0, pa1;
                lds_v2b64(aA + kpl * 512, pa0, pa1);
                uint32_t ax = xb + kpl * 8;
                #pragma unroll
                for (int cc = 0; cc < 4; cc++) {
                    int c = cc * 8 + cg2;
                    unsigned long long px = lds_b64(ax + c * 256);
                    acc[cc * 2]     = fma2(pa0, px, acc[cc * 2]);
                    acc[cc * 2 + 1] = fma2(pa1, px, acc[cc * 2 + 1]);
                }
            }
        }

        float Dh = Din[h];
        float* yp = d_yt + ((size_t)b * H_ + h) * L_;
        #pragma unroll
        for (int cc = 0; cc < 4; cc++) {
            int c = cc * 8 + cg2;
            int l0 = c * 64 + 2 * i2;
            float y0 = hsum2(acc[cc * 2])     + Dh * fsm[oU + l0];
            float y1 = hsum2(acc[cc * 2 + 1]) + Dh * fsm[oU + l0 + 1];
            *(float2*)(yp + l0) = make_float2(y0, y1);
        }
    }
}

// ---------------- launch -------------------------------------------------------
extern "C" void kernel_launch(void* const* d_in, const int* in_sizes, int n_in,
                              void* d_out, int out_size) {
    const float* u     = (const float*)d_in[0];
    const float* Lr    = (const float*)d_in[1];
    const float* Li    = (const float*)d_in[2];
    const float* Br    = (const float*)d_in[3];
    const float* Bi    = (const float*)d_in[4];
    const float* Cr    = (const float*)d_in[5];
    const float* Ci    = (const float*)d_in[6];
    const float* logdt = (const float*)d_in[7];
    const float* D     = (const float*)d_in[8];
    float* out = (float*)d_out;

    float* ut_ptr; cudaGetSymbolAddress((void**)&ut_ptr, d_ut);
    float* yt_ptr; cudaGetSymbolAddress((void**)&yt_ptr, d_yt);

    static const int FS_SMEM = FTOT * 4;   // 108544 bytes
    cudaFuncSetAttribute(fused_kernel, cudaFuncAttributeMaxDynamicSharedMemorySize, FS_SMEM);

    precompute_kernel<<<H_, N_>>>(Lr, Li, Br, Bi, Cr, Ci, logdt);
    transpose_BLH_to_BHL<<<dim3(H_ / 32, L_ / 32, B_), dim3(32, 8)>>>(u, ut_ptr);
    fused_kernel<<<dim3(B_, H_), 256, FS_SMEM>>>(D);
    transpose_BHL_to_BLH<<<dim3(L_ / 32, H_ / 32, B_), dim3(32, 8)>>>(yt_ptr, out);
}

// round 3
// speedup vs baseline: 3.0223x; 1.1361x over previous
#include <cuda_runtime.h>
#include <cuda_bf16.h>
#include <cstdint>

#define B_   16
#define L_   2048
#define H_   512
#define N_   64
#define C_   64
#define NCH  32   // L_/C_

// fused-kernel dynamic smem layout (float offsets)
#define oW   0                     // W interleaved: [n][65] float2  = 8320 floats
#define oA2  8320                  // A2 packed: [96][64] float2     = 12288 floats
#define oU   20608                 // u linear, 2 batches            = 4096 floats
#define oUT  24704                 // u_t [j=64][68]                 = 4352 floats
#define oXR  29056                 // [c=64][n=64]                   = 4096 floats
#define oXI  33152                 //                                = 4096 floats
#define FTOT 37248                 // 148992 bytes

// ---------------- scratch (__device__ globals) -------------------------------
__device__ __align__(16) float2 d_Wri[H_ * 64 * 65];   // [h][n][j(+pad)] (Re,Im) of Ab^{63-j}Bb
__device__ __align__(16) float2 d_A2p[H_ * 96 * 64];   // [h][kp][i] = (A2[2kp][i], A2[2kp+1][i])
__device__ __align__(16) float2 d_AbC[H_ * N_];        // Ab^C
__device__ __align__(16) float  d_ut [B_ * H_ * L_];   // u transposed (B,H,L)
__device__ __align__(16) float  d_yt [B_ * H_ * L_];   // y transposed (B,H,L)

__device__ __forceinline__ float2 cmul(float2 a, float2 b) {
    return make_float2(a.x * b.x - a.y * b.y, a.x * b.y + a.y * b.x);
}

// packed f32x2 helpers --------------------------------------------------------
__device__ __forceinline__ unsigned long long lds_b64(uint32_t a) {
    unsigned long long v;
    asm volatile("ld.shared.b64 %0, [%1];" : "=l"(v) : "r"(a));
    return v;
}
__device__ __forceinline__ void lds_v2b64(uint32_t a, unsigned long long& x, unsigned long long& y) {
    asm volatile("ld.shared.v2.u64 {%0,%1}, [%2];" : "=l"(x), "=l"(y) : "r"(a));
}
__device__ __forceinline__ unsigned long long fma2(unsigned long long a, unsigned long long b,
                                                   unsigned long long c) {
    unsigned long long d;
    asm("fma.rn.f32x2 %0, %1, %2, %3;" : "=l"(d) : "l"(a), "l"(b), "l"(c));
    return d;
}
__device__ __forceinline__ float hsum2(unsigned long long v) {
    float lo, hi;
    asm("mov.b64 {%0,%1}, %2;" : "=f"(lo), "=f"(hi) : "l"(v));
    return lo + hi;
}
__device__ __forceinline__ unsigned long long dup2(float x) {
    unsigned long long v;
    asm("mov.b64 %0, {%1, %1};" : "=l"(v) : "f"(x));
    return v;
}
__device__ __forceinline__ void unpack2(unsigned long long v, float& a, float& b) {
    asm("mov.b64 {%0,%1}, %2;" : "=f"(a), "=f"(b) : "l"(v));
}

// ---------------- precompute: discretization + packed operators --------------
__global__ void precompute_kernel(const float* __restrict__ Lr,
                                  const float* __restrict__ Li,
                                  const float* __restrict__ Br,
                                  const float* __restrict__ Bi,
                                  const float* __restrict__ Cr,
                                  const float* __restrict__ Ci,
                                  const float* __restrict__ logdt) {
    int h = blockIdx.x;
    int n = threadIdx.x;             // 64 threads
    int lane = n & 31, wid = n >> 5;

    float dt  = expf(logdt[h]);
    float lr  = Lr[n], li = Li[n];
    float er = expf(dt * lr);
    float s, c;
    sincosf(dt * li, &s, &c);
    float2 Ab = make_float2(er * c, er * s);

    // Bb = Bc*(Ab-1)/(Lambda+1e-8)
    float dr = lr + 1e-8f, di = li;
    float inv = 1.0f / (dr * dr + di * di);
    float2 Am1 = make_float2(Ab.x - 1.0f, Ab.y);
    float2 Bc  = make_float2(Br[h * N_ + n], Bi[h * N_ + n]);
    float2 num = cmul(Bc, Am1);
    float2 Bb  = make_float2((num.x * dr + num.y * di) * inv,
                             (num.y * dr - num.x * di) * inv);
    float2 Cc  = make_float2(Cr[h * N_ + n], Ci[h * N_ + n]);
    float2 CB  = cmul(Cc, Bb);

    __shared__ float sMr[64][65], sMi[64][65];
    __shared__ float sKpart[64][2];
    __shared__ float sKd[64];

    float2* wrow = d_Wri + (size_t)h * 64 * 65 + n * 65;

    float2 p = make_float2(1.0f, 0.0f);              // Ab^e
    for (int e = 0; e < C_; e++) {
        wrow[63 - e] = cmul(p, Bb);                  // W[n][j=63-e]
        float kv = CB.x * p.x - CB.y * p.y;          // Re(CB * Ab^e)
        #pragma unroll
        for (int off = 16; off; off >>= 1) kv += __shfl_xor_sync(0xffffffffu, kv, off);
        if (lane == 0) sKpart[e][wid] = kv;
        p = cmul(p, Ab);                             // Ab^{e+1}
        float2 m = cmul(Cc, p);
        sMr[e][n] = m.x;
        sMi[e][n] = m.y;
    }
    d_AbC[h * N_ + n] = p;                           // Ab^C
    __syncthreads();
    sKd[n] = sKpart[n][0] + sKpart[n][1];            // K[d=n]
    __syncthreads();

    // pack A2p[kp][i]: thread handles row i = n
    float2* A2g = d_A2p + (size_t)h * 96 * 64;
    #pragma unroll 4
    for (int kp = 0; kp < 32; kp++)                  // k in [0,64): Mr (times xr)
        A2g[kp * 64 + n] = make_float2(sMr[n][2 * kp], sMr[n][2 * kp + 1]);
    #pragma unroll 4
    for (int kp = 32; kp < 64; kp++)                 // k in [64,128): -Mi (times xi)
        A2g[kp * 64 + n] = make_float2(-sMi[n][2 * kp - 64], -sMi[n][2 * kp - 63]);
    #pragma unroll 4
    for (int kp = 64; kp < 96; kp++) {               // k in [128,192): Toeplitz K (times u)
        int j0 = 2 * (kp - 64);
        float v0 = (n >= j0)     ? sKd[n - j0]     : 0.0f;
        float v1 = (n >= j0 + 1) ? sKd[n - j0 - 1] : 0.0f;
        A2g[kp * 64 + n] = make_float2(v0, v1);
    }
}

// ---------------- transposes --------------------------------------------------
__global__ void transpose_BLH_to_BHL(const float* __restrict__ in, float* __restrict__ out) {
    __shared__ float tile[32][33];
    int b = blockIdx.z;
    int h0 = blockIdx.x * 32, l0 = blockIdx.y * 32;
    int tx = threadIdx.x, ty = threadIdx.y;   // (32, 8)
    #pragma unroll
    for (int k = 0; k < 4; k++) {
        int l = l0 + ty + k * 8;
        tile[ty + k * 8][tx] = in[((size_t)b * L_ + l) * H_ + h0 + tx];
    }
    __syncthreads();
    #pragma unroll
    for (int k = 0; k < 4; k++) {
        int h = h0 + ty + k * 8;
        out[((size_t)b * H_ + h) * L_ + l0 + tx] = tile[tx][ty + k * 8];
    }
}

__global__ void transpose_BHL_to_BLH(const float* __restrict__ in, float* __restrict__ out) {
    __shared__ float tile[32][33];
    int b = blockIdx.z;
    int l0 = blockIdx.x * 32, h0 = blockIdx.y * 32;
    int tx = threadIdx.x, ty = threadIdx.y;
    #pragma unroll
    for (int k = 0; k < 4; k++) {
        int h = h0 + ty + k * 8;
        tile[ty + k * 8][tx] = in[((size_t)b * H_ + h) * L_ + l0 + tx];
    }
    __syncthreads();
    #pragma unroll
    for (int k = 0; k < 4; k++) {
        int l = l0 + ty + k * 8;
        out[((size_t)b * L_ + l) * H_ + h0 + tx] = tile[tx][ty + k * 8];
    }
}

// ---------------- fused persistent-per-h kernel -------------------------------
extern __shared__ float fsm[];
__global__ __launch_bounds__(256) void fused_kernel(const float* __restrict__ Din) {
    int h     = blockIdx.y;
    int bbase = blockIdx.x * 8;       // 8 batches per block, 2 per iteration
    int tid   = threadIdx.x;

    // ---- stage operators once (W: 8320 floats, A2: 12288 floats)
    {
        const float4* src = (const float4*)(d_Wri + (size_t)h * 64 * 65);
        float4* dst = (float4*)(fsm + oW);
        for (int i = tid; i < 2080; i += 256) dst[i] = src[i];
    }
    {
        const float4* src = (const float4*)(d_A2p + (size_t)h * 96 * 64);
        float4* dst = (float4*)(fsm + oA2);
        for (int i = tid; i < 3072; i += 256) dst[i] = src[i];
    }
    float Dh = Din[h];

    uint32_t sb = (uint32_t)__cvta_generic_to_shared(fsm);

    for (int it = 0; it < 4; it++) {
        int b0 = bbase + it * 2;

        // ---- stage u (2 batches) + build u_t[j][c] in the same pass
        {
            const float4* s0 = (const float4*)(d_ut + ((size_t)b0 * H_ + h) * L_);
            const float4* s1 = (const float4*)(d_ut + ((size_t)(b0 + 1) * H_ + h) * L_);
            #pragma unroll
            for (int f = tid; f < 512; f += 256) {
                float4 v0 = s0[f];
                float4 v1 = s1[f];
                *(float4*)(fsm + oU + f * 4)        = v0;
                *(float4*)(fsm + oU + 2048 + f * 4) = v1;
                int j  = (f * 4) & 63;
                int c0 = (f * 4) >> 6;              // chunk within batch
                fsm[oUT + (j + 0) * 68 + c0] = v0.x;
                fsm[oUT + (j + 1) * 68 + c0] = v0.y;
                fsm[oUT + (j + 2) * 68 + c0] = v0.z;
                fsm[oUT + (j + 3) * 68 + c0] = v0.w;
                fsm[oUT + (j + 0) * 68 + 32 + c0] = v1.x;
                fsm[oUT + (j + 1) * 68 + 32 + c0] = v1.y;
                fsm[oUT + (j + 2) * 68 + 32 + c0] = v1.z;
                fsm[oUT + (j + 3) * 68 + 32 + c0] = v1.w;
            }
        }
        __syncthreads();

        // ---- phase 1: g[c][n] = sum_j W[n][j] * u[c][j]   (fma2 packed over c)
        {
            int n  = tid & 63;
            int cq = tid >> 6;                       // 16 consecutive c per thread
            uint32_t wb = sb + (oW + n * 130) * 4;   // W row (65 float2 = 130 floats)
            uint32_t ub = sb + (oUT + cq * 16) * 4;  // + j*272 bytes

            unsigned long long accr[8], acci[8];
            #pragma unroll
            for (int p = 0; p < 8; p++) { accr[p] = 0ull; acci[p] = 0ull; }

            #pragma unroll 4
            for (int j = 0; j < 64; j++) {
                unsigned long long wv = lds_b64(wb + j * 8);
                float wr, wi;
                unpack2(wv, wr, wi);
                unsigned long long wrd = dup2(wr);
                unsigned long long wid = dup2(wi);
                unsigned long long p0, p1, p2, p3, p4, p5, p6, p7;
                uint32_t ua = ub + j * 272;
                lds_v2b64(ua,      p0, p1);
                lds_v2b64(ua + 16, p2, p3);
                lds_v2b64(ua + 32, p4, p5);
                lds_v2b64(ua + 48, p6, p7);
                accr[0] = fma2(wrd, p0, accr[0]);  acci[0] = fma2(wid, p0, acci[0]);
                accr[1] = fma2(wrd, p1, accr[1]);  acci[1] = fma2(wid, p1, acci[1]);
                accr[2] = fma2(wrd, p2, accr[2]);  acci[2] = fma2(wid, p2, acci[2]);
                accr[3] = fma2(wrd, p3, accr[3]);  acci[3] = fma2(wid, p3, acci[3]);
                accr[4] = fma2(wrd, p4, accr[4]);  acci[4] = fma2(wid, p4, acci[4]);
                accr[5] = fma2(wrd, p5, accr[5]);  acci[5] = fma2(wid, p5, acci[5]);
                accr[6] = fma2(wrd, p6, accr[6]);  acci[6] = fma2(wid, p6, acci[6]);
                accr[7] = fma2(wrd, p7, accr[7]);  acci[7] = fma2(wid, p7, acci[7]);
            }
            #pragma unroll
            for (int p = 0; p < 8; p++) {
                int c = cq * 16 + 2 * p;
                float g0, g1;
                unpack2(accr[p], g0, g1);
                fsm[oXR + c * 64 + n]      = g0;
                fsm[oXR + c * 64 + 64 + n] = g1;
                unpack2(acci[p], g0, g1);
                fsm[oXI + c * 64 + n]      = g0;
                fsm[oXI + c * 64 + 64 + n] = g1;
            }
        }
        __syncthreads();

        // ---- phase 2: sequential scan over chunks (per batch), in place
        if (tid < 128) {
            int n  = tid & 63;
            int bb = tid >> 6;
            float2 a = d_AbC[h * N_ + n];
            float xr = 0.0f, xi = 0.0f;
            int cb = bb * 32;
            #pragma unroll 4
            for (int cl = 0; cl < NCH; cl++) {
                int c = cb + cl;
                float gr = fsm[oXR + c * 64 + n];
                float gi = fsm[oXI + c * 64 + n];
                fsm[oXR + c * 64 + n] = xr;
                fsm[oXI + c * 64 + n] = xi;
                float nxr = a.x * xr - a.y * xi + gr;
                xi = a.x * xi + a.y * xr + gi;
                xr = nxr;
            }
        }
        __syncthreads();

        // ---- phase 3: y[c][i] = A2(64x192) @ [xr;xi;u] + D*u   (fma2 packed over k)
        {
            int w    = tid >> 5, lane = tid & 31;
            int iw   = w & 3, cw = w >> 2;
            int i0   = iw * 16 + (lane & 3) * 4;     // 4 consecutive i
            int cbas = cw * 32 + (lane >> 2);        // c = cbas + 8*cc

            unsigned long long acc[16];
            #pragma unroll
            for (int k = 0; k < 16; k++) acc[k] = 0ull;

            uint32_t aB  = sb + oA2 * 4 + i0 * 8;
            uint32_t xrB = sb + oXR * 4 + cbas * 256;
            uint32_t xiB = sb + oXI * 4 + cbas * 256;
            uint32_t uB  = sb + oU  * 4 + cbas * 256;

            #pragma unroll 1
            for (int seg = 0; seg < 3; seg++) {
                uint32_t xb = (seg == 0) ? xrB : (seg == 1) ? xiB : uB;
                uint32_t aA = aB + seg * 32 * 512;
                #pragma unroll 4
                for (int kp = 0; kp < 32; kp++) {
                    unsigned long long pa0, pa1, pa2, pa3;
                    lds_v2b64(aA + kp * 512,      pa0, pa1);
                    lds_v2b64(aA + kp * 512 + 16, pa2, pa3);
                    uint32_t xk = xb + kp * 8;
                    #pragma unroll
                    for (int cc = 0; cc < 4; cc++) {
                        unsigned long long px = lds_b64(xk + cc * 2048);
                        acc[0 * 4 + cc] = fma2(pa0, px, acc[0 * 4 + cc]);
                        acc[1 * 4 + cc] = fma2(pa1, px, acc[1 * 4 + cc]);
                        acc[2 * 4 + cc] = fma2(pa2, px, acc[2 * 4 + cc]);
                        acc[3 * 4 + cc] = fma2(pa3, px, acc[3 * 4 + cc]);
                    }
                }
            }

            #pragma unroll
            for (int cc = 0; cc < 4; cc++) {
                int c = cbas + 8 * cc;
                float4 u4 = *(const float4*)(fsm + oU + c * 64 + i0);
                float4 y4;
                y4.x = hsum2(acc[0 * 4 + cc]) + Dh * u4.x;
                y4.y = hsum2(acc[1 * 4 + cc]) + Dh * u4.y;
                y4.z = hsum2(acc[2 * 4 + cc]) + Dh * u4.z;
                y4.w = hsum2(acc[3 * 4 + cc]) + Dh * u4.w;
                int b = b0 + (c >> 5);
                int l = (c & 31) * 64 + i0;
                *(float4*)(d_yt + ((size_t)b * H_ + h) * L_ + l) = y4;
            }
        }
        __syncthreads();   // u/XR/XI reused next iteration
    }
}

// ---------------- launch -------------------------------------------------------
extern "C" void kernel_launch(void* const* d_in, const int* in_sizes, int n_in,
                              void* d_out, int out_size) {
    const float* u     = (const float*)d_in[0];
    const float* Lr    = (const float*)d_in[1];
    const float* Li    = (const float*)d_in[2];
    const float* Br    = (const float*)d_in[3];
    const float* Bi    = (const float*)d_in[4];
    const float* Cr    = (const float*)d_in[5];
    const float* Ci    = (const float*)d_in[6];
    const float* logdt = (const float*)d_in[7];
    const float* D     = (const float*)d_in[8];
    float* out = (float*)d_out;

    float* ut_ptr; cudaGetSymbolAddress((void**)&ut_ptr, d_ut);
    float* yt_ptr; cudaGetSymbolAddress((void**)&yt_ptr, d_yt);

    static const int FS_SMEM = FTOT * 4;   // 148992 bytes
    cudaFuncSetAttribute(fused_kernel, cudaFuncAttributeMaxDynamicSharedMemorySize, FS_SMEM);

    precompute_kernel<<<H_, N_>>>(Lr, Li, Br, Bi, Cr, Ci, logdt);
    transpose_BLH_to_BHL<<<dim3(H_ / 32, L_ / 32, B_), dim3(32, 8)>>>(u, ut_ptr);
    fused_kernel<<<dim3(2, H_), 256, FS_SMEM>>>(D);
    transpose_BHL_to_BLH<<<dim3(L_ / 32, H_ / 32, B_), dim3(32, 8)>>>(yt_ptr, out);
}

// round 4
// speedup vs baseline: 3.8323x; 1.2680x over previous
#include <cuda_runtime.h>
#include <cuda_bf16.h>
#include <cstdint>

#define B_   16
#define L_   2048
#define H_   512
#define N_   64
#define C_   64
#define NCH  32   // L_/C_

// fused-kernel dynamic smem layout (float offsets)
#define oWr  0                     // Wr swizzled [n][64]            = 4096
#define oWi  4096                  // Wi swizzled [n][64]            = 4096
#define oA2  8192                  // A2 [64 kp][64 i] float2        = 8192
#define oKRA 16384                 // reversed K, odd-i copy         = 128
#define oKRB 16512                 // reversed K, even-i copy        = 128
#define oU   16640                 // u [c=32][68]                   = 2176
#define oXU  18816                 // u copy [c=32][66]              = 2112
#define oXR  20928                 // [c=32][66]                     = 2112
#define oXI  23040                 // [c=32][66]                     = 2112
#define FTOT 25152                 // 100608 bytes

// ---------------- scratch (__device__ globals) -------------------------------
__device__ __align__(16) float  d_Wswz[H_ * 8192];     // [h][plane r/i][n][64] xor-swizzled
__device__ __align__(16) float2 d_A2p [H_ * 64 * 64];  // [h][kp][i] (Mr | -Mi) k-pairs
__device__ __align__(16) float  d_KR  [H_ * 256];      // [h][KRA 128 | KRB 128]
__device__ __align__(16) float2 d_AbC [H_ * N_];       // Ab^C
__device__ __align__(16) float  d_ut  [B_ * H_ * L_];  // u transposed (B,H,L)
__device__ __align__(16) float  d_yt  [B_ * H_ * L_];  // y transposed (B,H,L)

__device__ __forceinline__ float2 cmul(float2 a, float2 b) {
    return make_float2(a.x * b.x - a.y * b.y, a.x * b.y + a.y * b.x);
}

typedef unsigned long long ull;
__device__ __forceinline__ ull lds_b64(uint32_t a) {
    ull v; asm volatile("ld.shared.b64 %0, [%1];" : "=l"(v) : "r"(a)); return v;
}
__device__ __forceinline__ void lds_v2b64(uint32_t a, ull& x, ull& y) {
    asm volatile("ld.shared.v2.u64 {%0,%1}, [%2];" : "=l"(x), "=l"(y) : "r"(a));
}
__device__ __forceinline__ ull fma2(ull a, ull b, ull c) {
    ull d; asm("fma.rn.f32x2 %0, %1, %2, %3;" : "=l"(d) : "l"(a), "l"(b), "l"(c)); return d;
}
__device__ __forceinline__ float hsum2(ull v) {
    float lo, hi; asm("mov.b64 {%0,%1}, %2;" : "=f"(lo), "=f"(hi) : "l"(v)); return lo + hi;
}

// ---------------- precompute: discretization + packed/swizzled operators -----
__global__ void precompute_kernel(const float* __restrict__ Lr,
                                  const float* __restrict__ Li,
                                  const float* __restrict__ Br,
                                  const float* __restrict__ Bi,
                                  const float* __restrict__ Cr,
                                  const float* __restrict__ Ci,
                                  const float* __restrict__ logdt) {
    int h = blockIdx.x;
    int n = threadIdx.x;             // 64 threads
    int lane = n & 31, wid = n >> 5;
    int nx = n & 31;

    float dt  = expf(logdt[h]);
    float lr  = Lr[n], li = Li[n];
    float er = expf(dt * lr);
    float s, c;
    sincosf(dt * li, &s, &c);
    float2 Ab = make_float2(er * c, er * s);

    float dr = lr + 1e-8f, di = li;
    float inv = 1.0f / (dr * dr + di * di);
    float2 Am1 = make_float2(Ab.x - 1.0f, Ab.y);
    float2 Bc  = make_float2(Br[h * N_ + n], Bi[h * N_ + n]);
    float2 num = cmul(Bc, Am1);
    float2 Bb  = make_float2((num.x * dr + num.y * di) * inv,
                             (num.y * dr - num.x * di) * inv);
    float2 Cc  = make_float2(Cr[h * N_ + n], Ci[h * N_ + n]);
    float2 CB  = cmul(Cc, Bb);

    __shared__ float sMr[64][65], sMi[64][65];
    __shared__ float sKpart[64][2];
    __shared__ float sKd[64];

    float* Wg = d_Wswz + (size_t)h * 8192;

    float2 p = make_float2(1.0f, 0.0f);              // Ab^e
    for (int e = 0; e < C_; e++) {
        float2 w = cmul(p, Bb);                      // W[j = 63-e][n]
        int j = 63 - e;
        int idx = n * 64 + 2 * ((j >> 1) ^ nx) + (j & 1);
        Wg[idx]        = w.x;
        Wg[4096 + idx] = w.y;
        float kv = CB.x * p.x - CB.y * p.y;          // Re(CB * Ab^e) = K[e]
        #pragma unroll
        for (int off = 16; off; off >>= 1) kv += __shfl_xor_sync(0xffffffffu, kv, off);
        if (lane == 0) sKpart[e][wid] = kv;
        p = cmul(p, Ab);                             // Ab^{e+1}
        float2 m = cmul(Cc, p);                      // M[i=e][n]
        sMr[e][n] = m.x;
        sMi[e][n] = m.y;
    }
    d_AbC[h * N_ + n] = p;                           // Ab^C
    __syncthreads();
    sKd[n] = sKpart[n][0] + sKpart[n][1];            // K[d = n]
    __syncthreads();

    // A2 [kp][i]: kp 0..31 -> Mr k-pairs; 32..63 -> -Mi k-pairs (thread = row i)
    float2* A2g = d_A2p + (size_t)h * 64 * 64;
    #pragma unroll 4
    for (int kp = 0; kp < 32; kp++)
        A2g[kp * 64 + n] = make_float2(sMr[n][2 * kp], sMr[n][2 * kp + 1]);
    #pragma unroll 4
    for (int kp = 32; kp < 64; kp++)
        A2g[kp * 64 + n] = make_float2(-sMi[n][2 * kp - 64], -sMi[n][2 * kp - 63]);

    // reversed-K arrays: KRA[t] = K[63-t] (t<=63 else 0), KRB[t] = K[62-t] (t<=62 else 0)
    float* KRg = d_KR + (size_t)h * 256;
    KRg[n]        = sKd[63 - n];
    KRg[64 + n]   = 0.0f;
    KRg[128 + n]  = (n <= 62) ? sKd[62 - n] : 0.0f;
    KRg[192 + n]  = 0.0f;
}

// ---------------- transposes --------------------------------------------------
__global__ void transpose_BLH_to_BHL(const float* __restrict__ in, float* __restrict__ out) {
    __shared__ float tile[32][33];
    int b = blockIdx.z;
    int h0 = blockIdx.x * 32, l0 = blockIdx.y * 32;
    int tx = threadIdx.x, ty = threadIdx.y;   // (32, 8)
    #pragma unroll
    for (int k = 0; k < 4; k++) {
        int l = l0 + ty + k * 8;
        tile[ty + k * 8][tx] = in[((size_t)b * L_ + l) * H_ + h0 + tx];
    }
    __syncthreads();
    #pragma unroll
    for (int k = 0; k < 4; k++) {
        int h = h0 + ty + k * 8;
        out[((size_t)b * H_ + h) * L_ + l0 + tx] = tile[tx][ty + k * 8];
    }
}

__global__ void transpose_BHL_to_BLH(const float* __restrict__ in, float* __restrict__ out) {
    __shared__ float tile[32][33];
    int b = blockIdx.z;
    int l0 = blockIdx.x * 32, h0 = blockIdx.y * 32;
    int tx = threadIdx.x, ty = threadIdx.y;
    #pragma unroll
    for (int k = 0; k < 4; k++) {
        int h = h0 + ty + k * 8;
        tile[ty + k * 8][tx] = in[((size_t)b * H_ + h) * L_ + l0 + tx];
    }
    __syncthreads();
    #pragma unroll
    for (int k = 0; k < 4; k++) {
        int l = l0 + ty + k * 8;
        out[((size_t)b * L_ + l) * H_ + h0 + tx] = tile[tx][ty + k * 8];
    }
}

// ---------------- fused per-(h) kernel, 1 batch per iteration ------------------
extern __shared__ float fsm[];
__global__ __launch_bounds__(256, 2) void fused_kernel(const float* __restrict__ Din) {
    int h     = blockIdx.y;
    int bbase = blockIdx.x * 4;
    int tid   = threadIdx.x;

    // ---- stage operators once: W 8192 + A2 8192 + KR 256 floats
    {
        const float4* s = (const float4*)(d_Wswz + (size_t)h * 8192);
        float4* d = (float4*)(fsm + oWr);
        for (int i = tid; i < 2048; i += 256) d[i] = s[i];
        s = (const float4*)(d_A2p + (size_t)h * 64 * 64);
        d = (float4*)(fsm + oA2);
        for (int i = tid; i < 2048; i += 256) d[i] = s[i];
        s = (const float4*)(d_KR + (size_t)h * 256);
        d = (float4*)(fsm + oKRA);
        if (tid < 64) d[tid] = s[tid];
    }
    float Dh = Din[h];
    float2 aC = make_float2(0.f, 0.f);
    if (tid < 64) aC = d_AbC[h * 64 + tid];

    uint32_t sb = (uint32_t)__cvta_generic_to_shared(fsm);

    for (int it = 0; it < 4; it++) {
        int b = bbase + it;

        // ---- stage u: U68 (phase1) + XU66 (phase3/skip)
        {
            const float4* s = (const float4*)(d_ut + ((size_t)b * H_ + h) * L_);
            #pragma unroll
            for (int f = tid; f < 512; f += 256) {
                float4 v = s[f];
                int c  = f >> 4;
                int j4 = (f & 15) * 4;
                *(float4*)(fsm + oU + c * 68 + j4) = v;
                *(float2*)(fsm + oXU + c * 66 + j4)     = make_float2(v.x, v.y);
                *(float2*)(fsm + oXU + c * 66 + j4 + 2) = make_float2(v.z, v.w);
            }
        }
        __syncthreads();

        // ---- phase 1: g[c][n] = sum_j W[j][n]*u[c][j]  (pack over j-parity)
        {
            int n  = tid & 63, nx = n & 31;
            int cq = tid >> 6;
            uint32_t wrB = sb + (oWr + n * 64) * 4;
            uint32_t wiB = wrB + 4096 * 4;
            uint32_t uB[8];
            #pragma unroll
            for (int cc = 0; cc < 8; cc++)
                uB[cc] = sb + (oU + (cq * 8 + cc) * 68) * 4;

            ull accr[8], acci[8];
            #pragma unroll
            for (int p = 0; p < 8; p++) { accr[p] = 0ull; acci[p] = 0ull; }

            #pragma unroll 4
            for (int jq = 0; jq < 16; jq++) {
                uint32_t g0 = (uint32_t)(((2 * jq) ^ nx) * 8);
                ull wr0 = lds_b64(wrB + g0);
                ull wr1 = lds_b64(wrB + (g0 ^ 8));
                ull wi0 = lds_b64(wiB + g0);
                ull wi1 = lds_b64(wiB + (g0 ^ 8));
                #pragma unroll
                for (int cc = 0; cc < 8; cc++) {
                    ull u0, u1;
                    lds_v2b64(uB[cc] + jq * 16, u0, u1);
                    accr[cc] = fma2(wr0, u0, accr[cc]);
                    accr[cc] = fma2(wr1, u1, accr[cc]);
                    acci[cc] = fma2(wi0, u0, acci[cc]);
                    acci[cc] = fma2(wi1, u1, acci[cc]);
                }
            }
            #pragma unroll
            for (int cc = 0; cc < 8; cc++) {
                int c = cq * 8 + cc;
                fsm[oXR + c * 66 + n] = hsum2(accr[cc]);
                fsm[oXI + c * 66 + n] = hsum2(acci[cc]);
            }
        }
        __syncthreads();

        // ---- phase 2: serial scan over 32 chunks (in-place g -> x-prefix)
        if (tid < 64) {
            int n = tid;
            float xr = 0.0f, xi = 0.0f;
            #pragma unroll 4
            for (int c = 0; c < NCH; c++) {
                float gr = fsm[oXR + c * 66 + n];
                float gi = fsm[oXI + c * 66 + n];
                fsm[oXR + c * 66 + n] = xr;
                fsm[oXI + c * 66 + n] = xi;
                float nxr = aC.x * xr - aC.y * xi + gr;
                xi = aC.x * xi + aC.y * xr + gi;
                xr = nxr;
            }
        }
        __syncthreads();

        // ---- phase 3: y = M_r@xr - M_i@xi + Toeplitz(K)@u + D*u
        {
            int w = tid >> 5, lane = tid & 31;
            int iw = w & 3, cw = w >> 2;
            int i0 = iw * 16 + (lane & 3) * 4;       // 4 consecutive i (even base)
            int c0 = cw * 16 + (lane >> 2);          // c = c0 + 8*cc, cc in {0,1}

            ull acc[8];
            #pragma unroll
            for (int k = 0; k < 8; k++) acc[k] = 0ull;

            uint32_t aB  = sb + oA2 * 4 + i0 * 8;    // + kp*512
            uint32_t xrB = sb + oXR * 4 + c0 * 264;  // + kpl*8 ; second c: +8*264
            uint32_t xiB = sb + oXI * 4 + c0 * 264;
            uint32_t xuB = sb + oXU * 4 + c0 * 264;

            // seg 0: Mr x xr   /  seg 1: -Mi x xi
            #pragma unroll 1
            for (int seg = 0; seg < 2; seg++) {
                uint32_t xb = (seg == 0) ? xrB : xiB;
                uint32_t aA = aB + seg * 32 * 512;
                #pragma unroll 4
                for (int kpl = 0; kpl < 32; kpl++) {
                    ull pa0, pa1, pa2, pa3;
                    lds_v2b64(aA + kpl * 512,      pa0, pa1);
                    lds_v2b64(aA + kpl * 512 + 16, pa2, pa3);
                    ull x0 = lds_b64(xb + kpl * 8);
                    ull x1 = lds_b64(xb + 8 * 264 + kpl * 8);
                    acc[0] = fma2(pa0, x0, acc[0]);  acc[1] = fma2(pa0, x1, acc[1]);
                    acc[2] = fma2(pa1, x0, acc[2]);  acc[3] = fma2(pa1, x1, acc[3]);
                    acc[4] = fma2(pa2, x0, acc[4]);  acc[5] = fma2(pa2, x1, acc[5]);
                    acc[6] = fma2(pa3, x0, acc[6]);  acc[7] = fma2(pa3, x1, acc[7]);
                }
            }
            // seg 2: Toeplitz(K) x u via reversed-K pairs
            {
                uint32_t kraB = sb + oKRA * 4;
                uint32_t krbB = sb + oKRB * 4;
                #pragma unroll 4
                for (int kpl = 0; kpl < 32; kpl++) {
                    uint32_t tb = (uint32_t)((62 - i0 + 2 * kpl) * 4);   // >= 8
                    ull k0 = lds_b64(krbB + tb);       // i0   (even)
                    ull k1 = lds_b64(kraB + tb);       // i0+1 (odd)
                    ull k2 = lds_b64(krbB + tb - 8);   // i0+2
                    ull k3 = lds_b64(kraB + tb - 8);   // i0+3
                    ull x0 = lds_b64(xuB + kpl * 8);
                    ull x1 = lds_b64(xuB + 8 * 264 + kpl * 8);
                    acc[0] = fma2(k0, x0, acc[0]);  acc[1] = fma2(k0, x1, acc[1]);
                    acc[2] = fma2(k1, x0, acc[2]);  acc[3] = fma2(k1, x1, acc[3]);
                    acc[4] = fma2(k2, x0, acc[4]);  acc[5] = fma2(k2, x1, acc[5]);
                    acc[6] = fma2(k3, x0, acc[6]);  acc[7] = fma2(k3, x1, acc[7]);
                }
            }

            #pragma unroll
            for (int cc = 0; cc < 2; cc++) {
                int c = c0 + 8 * cc;
                float2 ua = *(const float2*)(fsm + oXU + c * 66 + i0);
                float2 ub = *(const float2*)(fsm + oXU + c * 66 + i0 + 2);
                float4 y4;
                y4.x = hsum2(acc[0 + cc]) + Dh * ua.x;
                y4.y = hsum2(acc[2 + cc]) + Dh * ua.y;
                y4.z = hsum2(acc[4 + cc]) + Dh * ub.x;
                y4.w = hsum2(acc[6 + cc]) + Dh * ub.y;
                *(float4*)(d_yt + ((size_t)b * H_ + h) * L_ + c * 64 + i0) = y4;
            }
        }
        __syncthreads();   // before next iteration's staging overwrites U/XU
    }
}

// ---------------- launch -------------------------------------------------------
extern "C" void kernel_launch(void* const* d_in, const int* in_sizes, int n_in,
                              void* d_out, int out_size) {
    const float* u     = (const float*)d_in[0];
    const float* Lr    = (const float*)d_in[1];
    const float* Li    = (const float*)d_in[2];
    const float* Br    = (const float*)d_in[3];
    const float* Bi    = (const float*)d_in[4];
    const float* Cr    = (const float*)d_in[5];
    const float* Ci    = (const float*)d_in[6];
    const float* logdt = (const float*)d_in[7];
    const float* D     = (const float*)d_in[8];
    float* out = (float*)d_out;

    float* ut_ptr; cudaGetSymbolAddress((void**)&ut_ptr, d_ut);
    float* yt_ptr; cudaGetSymbolAddress((void**)&yt_ptr, d_yt);

    static const int FS_SMEM = FTOT * 4;   // 100608 bytes -> 2 blocks/SM
    cudaFuncSetAttribute(fused_kernel, cudaFuncAttributeMaxDynamicSharedMemorySize, FS_SMEM);

    precompute_kernel<<<H_, N_>>>(Lr, Li, Br, Bi, Cr, Ci, logdt);
    transpose_BLH_to_BHL<<<dim3(H_ / 32, L_ / 32, B_), dim3(32, 8)>>>(u, ut_ptr);
    fused_kernel<<<dim3(4, H_), 256, FS_SMEM>>>(D);
    transpose_BHL_to_BLH<<<dim3(L_ / 32, H_ / 32, B_), dim3(32, 8)>>>(yt_ptr, out);
}

// round 6
// speedup vs baseline: 4.0845x; 1.0658x over previous
#include <cuda_runtime.h>
#include <cuda_bf16.h>
#include <cstdint>

#define B_   16
#define L_   2048
#define H_   512
#define N_   64

// ---------------- fused-kernel dynamic smem layout (byte offsets) ------------
#define oWH  0          // W hi [128][72] bf16 = 18432 B
#define oWL  18432      // W lo
#define oA2  36864      // A2: seg{0,1,2} x {hi,lo}, each [64][72] bf16 = 9216 B
#define oU   92160      // u tiles: 2 bufs x (hi [32][72] + lo [32][72]) = 2 x 9216
#define oX   110592     // X tiles: xrH, xrL, xiH, xiL each [32][72] = 4 x 4608
#define oD1  129024     // fp32 exchange [128][33] = 16896 B (reused as D2 [64][33])
#define SMEM_TOTAL 145920

// ---------------- scratch (__device__ globals) --------------------------------
__device__ __align__(16) __nv_bfloat16 gW  [H_ * 18432];   // per h: WH 9216 | WL 9216
__device__ __align__(16) __nv_bfloat16 gA2 [H_ * 27648];   // per h: A0H A0L A1H A1L A2H A2L
__device__ __align__(16) float2 d_AbC[H_ * N_];             // Ab^C
__device__ __align__(16) float  d_ut [B_ * H_ * L_];        // u transposed (B,H,L)
__device__ __align__(16) float  d_yt [B_ * H_ * L_];        // y transposed (B,H,L)

__device__ __forceinline__ float2 cmul(float2 a, float2 b) {
    return make_float2(a.x * b.x - a.y * b.y, a.x * b.y + a.y * b.x);
}

// ---------------- PTX helpers (compute_80+; valid on plain sm_103) -----------
__device__ __forceinline__ uint32_t smem_to_u32(const void* p) {
    uint32_t a;
    asm("{ .reg .u64 t; cvta.to.shared.u64 t, %1; cvt.u32.u64 %0, t; }" : "=r"(a) : "l"(p));
    return a;
}
__device__ __forceinline__ void ldm_x4(uint32_t* r, uint32_t addr) {
    asm volatile("ldmatrix.sync.aligned.m8n8.x4.shared.b16 {%0,%1,%2,%3}, [%4];"
                 : "=r"(r[0]), "=r"(r[1]), "=r"(r[2]), "=r"(r[3]) : "r"(addr));
}
__device__ __forceinline__ void ldm_x2(uint32_t* r, uint32_t addr) {
    asm volatile("ldmatrix.sync.aligned.m8n8.x2.shared.b16 {%0,%1}, [%2];"
                 : "=r"(r[0]), "=r"(r[1]) : "r"(addr));
}
__device__ __forceinline__ void mma16816(float* d, const uint32_t* a, const uint32_t* b) {
    asm volatile("mma.sync.aligned.m16n8k16.row.col.f32.bf16.bf16.f32 "
                 "{%0,%1,%2,%3}, {%4,%5,%6,%7}, {%8,%9}, {%0,%1,%2,%3};"
                 : "+f"(d[0]), "+f"(d[1]), "+f"(d[2]), "+f"(d[3])
                 : "r"(a[0]), "r"(a[1]), "r"(a[2]), "r"(a[3]), "r"(b[0]), "r"(b[1]));
}

// split fp32 into bf16 hi/lo
__device__ __forceinline__ void put2(__nv_bfloat16* th, __nv_bfloat16* tl, int idx, float v) {
    __nv_bfloat16 hv = __float2bfloat16(v);
    th[idx] = hv;
    tl[idx] = __float2bfloat16(v - __bfloat162float(hv));
}

// ---------------- precompute: discretization + padded bf16x2 operators --------
__global__ void precompute_kernel(const float* __restrict__ Lr,
                                  const float* __restrict__ Li,
                                  const float* __restrict__ Br,
                                  const float* __restrict__ Bi,
                                  const float* __restrict__ Cr,
                                  const float* __restrict__ Ci,
                                  const float* __restrict__ logdt,
                                  const float* __restrict__ Din) {
    int h = blockIdx.x;
    int n = threadIdx.x;             // 64 threads
    int lane = n & 31, wid = n >> 5;

    float dt  = expf(logdt[h]);
    float lr  = Lr[n], li = Li[n];
    float er = expf(dt * lr);
    float s, c;
    sincosf(dt * li, &s, &c);
    float2 Ab = make_float2(er * c, er * s);

    float dr = lr + 1e-8f, di = li;
    float inv = 1.0f / (dr * dr + di * di);
    float2 Am1 = make_float2(Ab.x - 1.0f, Ab.y);
    float2 Bc  = make_float2(Br[h * N_ + n], Bi[h * N_ + n]);
    float2 num = cmul(Bc, Am1);
    float2 Bb  = make_float2((num.x * dr + num.y * di) * inv,
                             (num.y * dr - num.x * di) * inv);
    float2 Cc  = make_float2(Cr[h * N_ + n], Ci[h * N_ + n]);
    float2 CB  = cmul(Cc, Bb);

    __shared__ float sKpart[64][2];
    __shared__ float sKd[64];

    __nv_bfloat16* WH  = gW + (size_t)h * 18432;
    __nv_bfloat16* WL  = WH + 9216;
    __nv_bfloat16* A0H = gA2 + (size_t)h * 27648;
    __nv_bfloat16* A0L = A0H + 4608;
    __nv_bfloat16* A1H = A0H + 9216;
    __nv_bfloat16* A1L = A0H + 13824;
    __nv_bfloat16* A2H = A0H + 18432;
    __nv_bfloat16* A2L = A0H + 23040;

    float2 p = make_float2(1.0f, 0.0f);              // Ab^e
    for (int e = 0; e < 64; e++) {
        float2 w = cmul(p, Bb);                      // = Ab^{63-j} Bb at j = 63-e
        int j = 63 - e;
        put2(WH, WL, n * 72 + j, w.x);               // A1 rows 0..63 : real
        put2(WH, WL, (64 + n) * 72 + j, w.y);        // rows 64..127 : imag
        float kv = CB.x * p.x - CB.y * p.y;          // K[e] partial (this n)
        #pragma unroll
        for (int off = 16; off; off >>= 1) kv += __shfl_xor_sync(0xffffffffu, kv, off);
        if (lane == 0) sKpart[e][wid] = kv;
        p = cmul(p, Ab);                             // Ab^{e+1}
        float2 m = cmul(Cc, p);                      // M[i=e][n]
        put2(A0H, A0L, e * 72 + n, m.x);             // seg0: Mr
        put2(A1H, A1L, e * 72 + n, -m.y);            // seg1: -Mi
    }
    d_AbC[h * N_ + n] = p;                           // Ab^C
    __syncthreads();
    sKd[n] = sKpart[n][0] + sKpart[n][1];            // K[d = n]
    __syncthreads();

    float Dh = Din[h];
    for (int i = 0; i < 64; i++) {                   // seg2: Toeplitz + D on diagonal
        float v = (i > n) ? sKd[i - n] : (i == n ? sKd[0] + Dh : 0.0f);
        put2(A2H, A2L, i * 72 + n, v);
    }
}

// ---------------- transposes ---------------------------------------------------
__global__ void transpose_BLH_to_BHL(const float* __restrict__ in, float* __restrict__ out) {
    __shared__ float tile[32][33];
    int b = blockIdx.z;
    int h0 = blockIdx.x * 32, l0 = blockIdx.y * 32;
    int tx = threadIdx.x, ty = threadIdx.y;   // (32, 8)
    #pragma unroll
    for (int k = 0; k < 4; k++) {
        int l = l0 + ty + k * 8;
        tile[ty + k * 8][tx] = in[((size_t)b * L_ + l) * H_ + h0 + tx];
    }
    __syncthreads();
    #pragma unroll
    for (int k = 0; k < 4; k++) {
        int h = h0 + ty + k * 8;
        out[((size_t)b * H_ + h) * L_ + l0 + tx] = tile[tx][ty + k * 8];
    }
}

__global__ void transpose_BHL_to_BLH(const float* __restrict__ in, float* __restrict__ out) {
    __shared__ float tile[32][33];
    int b = blockIdx.z;
    int l0 = blockIdx.x * 32, h0 = blockIdx.y * 32;
    int tx = threadIdx.x, ty = threadIdx.y;
    #pragma unroll
    for (int k = 0; k < 4; k++) {
        int h = h0 + ty + k * 8;
        tile[ty + k * 8][tx] = in[((size_t)b * H_ + h) * L_ + l0 + tx];
    }
    __syncthreads();
    #pragma unroll
    for (int k = 0; k < 4; k++) {
        int l = l0 + ty + k * 8;
        out[((size_t)b * L_ + l) * H_ + h0 + tx] = tile[tx][ty + k * 8];
    }
}

// ---------------- u staging: fp32 -> bf16 hi/lo padded tile -------------------
__device__ __forceinline__ void stage_u(char* smc, const float* __restrict__ up,
                                        int buf, int tstart, int tstep) {
    const float4* s = (const float4*)up;
    __nv_bfloat16* uh = (__nv_bfloat16*)(smc + oU + buf * 9216);
    __nv_bfloat16* ul = uh + 2304;
    for (int f = tstart; f < 512; f += tstep) {
        float4 v = s[f];
        int idx = (f >> 4) * 72 + (f & 15) * 4;      // [chunk][time]
        __nv_bfloat16 h0 = __float2bfloat16(v.x), h1 = __float2bfloat16(v.y);
        __nv_bfloat16 h2 = __float2bfloat16(v.z), h3 = __float2bfloat16(v.w);
        __nv_bfloat162 p0; p0.x = h0; p0.y = h1;
        __nv_bfloat162 p1; p1.x = h2; p1.y = h3;
        *(__nv_bfloat162*)(uh + idx)     = p0;
        *(__nv_bfloat162*)(uh + idx + 2) = p1;
        __nv_bfloat162 q0, q1;
        q0.x = __float2bfloat16(v.x - __bfloat162float(h0));
        q0.y = __float2bfloat16(v.y - __bfloat162float(h1));
        q1.x = __float2bfloat16(v.z - __bfloat162float(h2));
        q1.y = __float2bfloat16(v.w - __bfloat162float(h3));
        *(__nv_bfloat162*)(ul + idx)     = q0;
        *(__nv_bfloat162*)(ul + idx + 2) = q1;
    }
}

// ---------------- fused HMMA kernel: one block per (h, 8 batches) -------------
extern __shared__ char smc[];
__global__ __launch_bounds__(256) void fused_kernel() {
    int h   = blockIdx.y;
    int b0  = blockIdx.x * 8;
    int tid = threadIdx.x;
    int w   = tid >> 5, lane = tid & 31;

    uint32_t sb = smem_to_u32(smc);

    // ---- stage operators: W 36864 B + A2 55296 B
    {
        const float4* s = (const float4*)(gW + (size_t)h * 18432);
        float4* d = (float4*)(smc + oWH);
        for (int i = tid; i < 2304; i += 256) d[i] = s[i];
        s = (const float4*)(gA2 + (size_t)h * 27648);
        d = (float4*)(smc + oA2);
        for (int i = tid; i < 3456; i += 256) d[i] = s[i];
    }
    float2 aC = make_float2(0.f, 0.f);
    if (tid < 64) aC = d_AbC[h * 64 + tid];
    stage_u(smc, d_ut + ((size_t)b0 * H_ + h) * L_, 0, tid, 256);
    __syncthreads();

    // ldmatrix lane address offsets (within a tile, bytes)
    uint32_t laneA = (uint32_t)(((lane & 15) * 72 + (lane >> 4) * 8) * 2);
    uint32_t laneB = (uint32_t)(((lane & 7) * 72 + ((lane >> 3) & 1) * 8) * 2);

    float* sD1 = (float*)(smc + oD1);

    for (int it = 0; it < 8; it++) {
        int b = b0 + it, buf = it & 1;
        uint32_t uhB = sb + oU + buf * 9216 + laneB;
        uint32_t ulB = uhB + 4608;

        // ---- MMA1: D1[128,32] = Wstack[128,64] @ u[32,64]^T  (bf16x3)
        {
            int m0 = w * 16;
            uint32_t aHB = sb + oWH + (uint32_t)(m0 * 144) + laneA;
            uint32_t aLB = aHB + 18432;
            float acc[16];
            #pragma unroll
            for (int i = 0; i < 16; i++) acc[i] = 0.f;
            #pragma unroll
            for (int kt = 0; kt < 4; kt++) {
                uint32_t ko = kt * 32;
                uint32_t aH[4], aL[4];
                ldm_x4(aH, aHB + ko);
                ldm_x4(aL, aLB + ko);
                #pragma unroll
                for (int nt = 0; nt < 4; nt++) {
                    uint32_t bo = nt * 1152 + ko;
                    uint32_t bh[2], bl[2];
                    ldm_x2(bh, uhB + bo);
                    ldm_x2(bl, ulB + bo);
                    mma16816(acc + nt * 4, aH, bh);
                    mma16816(acc + nt * 4, aH, bl);
                    mma16816(acc + nt * 4, aL, bh);
                }
            }
            int gid = lane >> 2, tq = lane & 3;
            #pragma unroll
            for (int nt = 0; nt < 4; nt++) {
                int c0 = nt * 8 + tq * 2;
                int r0 = m0 + gid;
                sD1[r0 * 33 + c0]           = acc[nt * 4 + 0];
                sD1[r0 * 33 + c0 + 1]       = acc[nt * 4 + 1];
                sD1[(r0 + 8) * 33 + c0]     = acc[nt * 4 + 2];
                sD1[(r0 + 8) * 33 + c0 + 1] = acc[nt * 4 + 3];
            }
        }
        __syncthreads();

        // ---- scan (warps 0,1) emit X tiles; warps 2-7 stage next u
        if (tid < 64) {
            __nv_bfloat16* xrH = (__nv_bfloat16*)(smc + oX);
            __nv_bfloat16* xrL = xrH + 2304;
            __nv_bfloat16* xiH = xrH + 4608;
            __nv_bfloat16* xiL = xrH + 6912;
            float xr = 0.f, xi = 0.f;
            #pragma unroll 4
            for (int c = 0; c < 32; c++) {
                float gr = sD1[tid * 33 + c];
                float gi = sD1[(64 + tid) * 33 + c];
                int idx = c * 72 + tid;
                __nv_bfloat16 hr = __float2bfloat16(xr);
                xrH[idx] = hr;
                xrL[idx] = __float2bfloat16(xr - __bfloat162float(hr));
                __nv_bfloat16 hi = __float2bfloat16(xi);
                xiH[idx] = hi;
                xiL[idx] = __float2bfloat16(xi - __bfloat162float(hi));
                float nx = aC.x * xr - aC.y * xi + gr;
                xi = aC.x * xi + aC.y * xr + gi;
                xr = nx;
            }
        } else if (it + 1 < 8) {
            stage_u(smc, d_ut + ((size_t)(b + 1) * H_ + h) * L_, buf ^ 1, tid - 64, 192);
        }
        __syncthreads();

        // ---- MMA2: D2[64,32] = A2[64,192] @ [xr|xi|u]^T  (3 segs x bf16x3)
        {
            int m0 = (w & 3) * 16, nh = w >> 2;
            float acc[8];
            #pragma unroll
            for (int i = 0; i < 8; i++) acc[i] = 0.f;
            #pragma unroll
            for (int seg = 0; seg < 3; seg++) {
                uint32_t aHB = sb + oA2 + (uint32_t)(seg * 18432 + m0 * 144) + laneA;
                uint32_t aLB = aHB + 9216;
                uint32_t bHB = (seg == 2) ? uhB : (sb + oX + (uint32_t)(seg * 9216) + laneB);
                uint32_t bLB = bHB + 4608;
                #pragma unroll
                for (int kt = 0; kt < 4; kt++) {
                    uint32_t ko = kt * 32;
                    uint32_t aH[4], aL[4];
                    ldm_x4(aH, aHB + ko);
                    ldm_x4(aL, aLB + ko);
                    #pragma unroll
                    for (int nt = 0; nt < 2; nt++) {
                        uint32_t bo = (uint32_t)((nh * 2 + nt) * 1152) + ko;
                        uint32_t bh[2], bl[2];
                        ldm_x2(bh, bHB + bo);
                        ldm_x2(bl, bLB + bo);
                        mma16816(acc + nt * 4, aH, bh);
                        mma16816(acc + nt * 4, aH, bl);
                        mma16816(acc + nt * 4, aL, bh);
                    }
                }
            }
            int gid = lane >> 2, tq = lane & 3;
            #pragma unroll
            for (int nt = 0; nt < 2; nt++) {
                int c0 = nh * 16 + nt * 8 + tq * 2;
                int i0 = m0 + gid;
                sD1[i0 * 33 + c0]           = acc[nt * 4 + 0];
                sD1[i0 * 33 + c0 + 1]       = acc[nt * 4 + 1];
                sD1[(i0 + 8) * 33 + c0]     = acc[nt * 4 + 2];
                sD1[(i0 + 8) * 33 + c0 + 1] = acc[nt * 4 + 3];
            }
        }
        __syncthreads();

        // ---- coalesced store: y[l = c*64+i] = D2[i][c]
        {
            float* yp = d_yt + ((size_t)b * H_ + h) * L_;
            #pragma unroll
            for (int rep = 0; rep < 8; rep++) {
                int idx = rep * 256 + tid;
                yp[idx] = sD1[(idx & 63) * 33 + (idx >> 6)];
            }
        }
        __syncthreads();
    }
}

// ---------------- launch --------------------------------------------------------
extern "C" void kernel_launch(void* const* d_in, const int* in_sizes, int n_in,
                              void* d_out, int out_size) {
    const float* u     = (const float*)d_in[0];
    const float* Lr    = (const float*)d_in[1];
    const float* Li    = (const float*)d_in[2];
    const float* Br    = (const float*)d_in[3];
    const float* Bi    = (const float*)d_in[4];
    const float* Cr    = (const float*)d_in[5];
    const float* Ci    = (const float*)d_in[6];
    const float* logdt = (const float*)d_in[7];
    const float* D     = (const float*)d_in[8];
    float* out = (float*)d_out;

    float* ut_ptr; cudaGetSymbolAddress((void**)&ut_ptr, d_ut);
    float* yt_ptr; cudaGetSymbolAddress((void**)&yt_ptr, d_yt);

    cudaFuncSetAttribute(fused_kernel, cudaFuncAttributeMaxDynamicSharedMemorySize, SMEM_TOTAL);

    precompute_kernel<<<H_, N_>>>(Lr, Li, Br, Bi, Cr, Ci, logdt, D);
    transpose_BLH_to_BHL<<<dim3(H_ / 32, L_ / 32, B_), dim3(32, 8)>>>(u, ut_ptr);
    fused_kernel<<<dim3(2, H_), 256, SMEM_TOTAL>>>();
    transpose_BHL_to_BLH<<<dim3(L_ / 32, H_ / 32, B_), dim3(32, 8)>>>(yt_ptr, out);
}

// round 7
// speedup vs baseline: 4.2148x; 1.0319x over previous
#include <cuda_runtime.h>
#include <cuda_bf16.h>
#include <cstdint>

#define B_   16
#define L_   2048
#define H_   512
#define N_   64

// ---------------- fused-kernel dynamic smem layout (byte offsets) ------------
#define oWH  0          // W hi [128][72] bf16 = 18432 B
#define oWL  18432      // W lo
#define oA2  36864      // A2: seg{0,1,2} x {hi,lo}, each [64][72] bf16 = 9216 B
#define oU   92160      // u tiles: 2 bufs x (hi [32][72] + lo [32][72]) = 2 x 9216
#define oX   110592     // X tiles: xrH, xrL, xiH, xiL each [32][72] = 4 x 4608
#define oD1  129024     // fp32 exchange [128][33] = 16896 B (reused as D2 [64][33])
#define SMEM_TOTAL 145920

// ---------------- scratch (__device__ globals) --------------------------------
__device__ __align__(16) __nv_bfloat16 gW  [H_ * 18432];   // per h: WH 9216 | WL 9216
__device__ __align__(16) __nv_bfloat16 gA2 [H_ * 27648];   // per h: A0H A0L A1H A1L A2H A2L
__device__ __align__(16) float2 d_AbC[H_ * N_];             // Ab^C
__device__ __align__(16) float  d_ut [B_ * H_ * L_];        // u transposed (B,H,L)
__device__ __align__(16) float  d_yt [B_ * H_ * L_];        // y transposed (B,H,L)

__device__ __forceinline__ float2 cmul(float2 a, float2 b) {
    return make_float2(a.x * b.x - a.y * b.y, a.x * b.y + a.y * b.x);
}

// ---------------- PTX helpers (compute_80+; valid on plain sm_103) -----------
__device__ __forceinline__ uint32_t smem_to_u32(const void* p) {
    uint32_t a;
    asm("{ .reg .u64 t; cvta.to.shared.u64 t, %1; cvt.u32.u64 %0, t; }" : "=r"(a) : "l"(p));
    return a;
}
__device__ __forceinline__ void ldm_x4(uint32_t* r, uint32_t addr) {
    asm volatile("ldmatrix.sync.aligned.m8n8.x4.shared.b16 {%0,%1,%2,%3}, [%4];"
                 : "=r"(r[0]), "=r"(r[1]), "=r"(r[2]), "=r"(r[3]) : "r"(addr));
}
__device__ __forceinline__ void ldm_x2(uint32_t* r, uint32_t addr) {
    asm volatile("ldmatrix.sync.aligned.m8n8.x2.shared.b16 {%0,%1}, [%2];"
                 : "=r"(r[0]), "=r"(r[1]) : "r"(addr));
}
__device__ __forceinline__ void mma16816(float* d, const uint32_t* a, const uint32_t* b) {
    asm volatile("mma.sync.aligned.m16n8k16.row.col.f32.bf16.bf16.f32 "
                 "{%0,%1,%2,%3}, {%4,%5,%6,%7}, {%8,%9}, {%0,%1,%2,%3};"
                 : "+f"(d[0]), "+f"(d[1]), "+f"(d[2]), "+f"(d[3])
                 : "r"(a[0]), "r"(a[1]), "r"(a[2]), "r"(a[3]), "r"(b[0]), "r"(b[1]));
}

// split fp32 into bf16 hi/lo
__device__ __forceinline__ void put2(__nv_bfloat16* th, __nv_bfloat16* tl, int idx, float v) {
    __nv_bfloat16 hv = __float2bfloat16(v);
    th[idx] = hv;
    tl[idx] = __float2bfloat16(v - __bfloat162float(hv));
}

// ---------------- precompute: discretization + padded bf16x2 operators --------
__global__ void precompute_kernel(const float* __restrict__ Lr,
                                  const float* __restrict__ Li,
                                  const float* __restrict__ Br,
                                  const float* __restrict__ Bi,
                                  const float* __restrict__ Cr,
                                  const float* __restrict__ Ci,
                                  const float* __restrict__ logdt,
                                  const float* __restrict__ Din) {
    int h = blockIdx.x;
    int n = threadIdx.x;             // 64 threads
    int lane = n & 31, wid = n >> 5;

    float dt  = expf(logdt[h]);
    float lr  = Lr[n], li = Li[n];
    float er = expf(dt * lr);
    float s, c;
    sincosf(dt * li, &s, &c);
    float2 Ab = make_float2(er * c, er * s);

    float dr = lr + 1e-8f, di = li;
    float inv = 1.0f / (dr * dr + di * di);
    float2 Am1 = make_float2(Ab.x - 1.0f, Ab.y);
    float2 Bc  = make_float2(Br[h * N_ + n], Bi[h * N_ + n]);
    float2 num = cmul(Bc, Am1);
    float2 Bb  = make_float2((num.x * dr + num.y * di) * inv,
                             (num.y * dr - num.x * di) * inv);
    float2 Cc  = make_float2(Cr[h * N_ + n], Ci[h * N_ + n]);
    float2 CB  = cmul(Cc, Bb);

    __shared__ float sKpart[64][2];
    __shared__ float sKd[64];

    __nv_bfloat16* WH  = gW + (size_t)h * 18432;
    __nv_bfloat16* WL  = WH + 9216;
    __nv_bfloat16* A0H = gA2 + (size_t)h * 27648;
    __nv_bfloat16* A0L = A0H + 4608;
    __nv_bfloat16* A1H = A0H + 9216;
    __nv_bfloat16* A1L = A0H + 13824;
    __nv_bfloat16* A2H = A0H + 18432;
    __nv_bfloat16* A2L = A0H + 23040;

    float2 p = make_float2(1.0f, 0.0f);              // Ab^e
    for (int e = 0; e < 64; e++) {
        float2 w = cmul(p, Bb);                      // = Ab^{63-j} Bb at j = 63-e
        int j = 63 - e;
        put2(WH, WL, n * 72 + j, w.x);               // rows 0..63 : real
        put2(WH, WL, (64 + n) * 72 + j, w.y);        // rows 64..127 : imag
        float kv = CB.x * p.x - CB.y * p.y;          // K[e] partial (this n)
        #pragma unroll
        for (int off = 16; off; off >>= 1) kv += __shfl_xor_sync(0xffffffffu, kv, off);
        if (lane == 0) sKpart[e][wid] = kv;
        p = cmul(p, Ab);                             // Ab^{e+1}
        float2 m = cmul(Cc, p);                      // M[i=e][n]
        put2(A0H, A0L, e * 72 + n, m.x);             // seg0: Mr
        put2(A1H, A1L, e * 72 + n, -m.y);            // seg1: -Mi
    }
    d_AbC[h * N_ + n] = p;                           // Ab^C
    __syncthreads();
    sKd[n] = sKpart[n][0] + sKpart[n][1];            // K[d = n]
    __syncthreads();

    float Dh = Din[h];
    for (int i = 0; i < 64; i++) {                   // seg2: Toeplitz + D on diagonal
        float v = (i > n) ? sKd[i - n] : (i == n ? sKd[0] + Dh : 0.0f);
        put2(A2H, A2L, i * 72 + n, v);
    }
}

// ---------------- transposes ---------------------------------------------------
__global__ void transpose_BLH_to_BHL(const float* __restrict__ in, float* __restrict__ out) {
    __shared__ float tile[32][33];
    int b = blockIdx.z;
    int h0 = blockIdx.x * 32, l0 = blockIdx.y * 32;
    int tx = threadIdx.x, ty = threadIdx.y;   // (32, 8)
    #pragma unroll
    for (int k = 0; k < 4; k++) {
        int l = l0 + ty + k * 8;
        tile[ty + k * 8][tx] = in[((size_t)b * L_ + l) * H_ + h0 + tx];
    }
    __syncthreads();
    #pragma unroll
    for (int k = 0; k < 4; k++) {
        int h = h0 + ty + k * 8;
        out[((size_t)b * H_ + h) * L_ + l0 + tx] = tile[tx][ty + k * 8];
    }
}

__global__ void transpose_BHL_to_BLH(const float* __restrict__ in, float* __restrict__ out) {
    __shared__ float tile[32][33];
    int b = blockIdx.z;
    int l0 = blockIdx.x * 32, h0 = blockIdx.y * 32;
    int tx = threadIdx.x, ty = threadIdx.y;
    #pragma unroll
    for (int k = 0; k < 4; k++) {
        int h = h0 + ty + k * 8;
        tile[ty + k * 8][tx] = in[((size_t)b * H_ + h) * L_ + l0 + tx];
    }
    __syncthreads();
    #pragma unroll
    for (int k = 0; k < 4; k++) {
        int l = l0 + ty + k * 8;
        out[((size_t)b * L_ + l) * H_ + h0 + tx] = tile[tx][ty + k * 8];
    }
}

// ---------------- u staging: fp32 -> bf16 hi/lo padded tile -------------------
__device__ __forceinline__ void stage_u(char* smc, const float* __restrict__ up,
                                        int buf, int tstart, int tstep) {
    const float4* s = (const float4*)up;
    __nv_bfloat16* uh = (__nv_bfloat16*)(smc + oU + buf * 9216);
    __nv_bfloat16* ul = uh + 2304;
    for (int f = tstart; f < 512; f += tstep) {
        float4 v = s[f];
        int idx = (f >> 4) * 72 + (f & 15) * 4;      // [chunk][time]
        __nv_bfloat16 h0 = __float2bfloat16(v.x), h1 = __float2bfloat16(v.y);
        __nv_bfloat16 h2 = __float2bfloat16(v.z), h3 = __float2bfloat16(v.w);
        __nv_bfloat162 p0; p0.x = h0; p0.y = h1;
        __nv_bfloat162 p1; p1.x = h2; p1.y = h3;
        *(__nv_bfloat162*)(uh + idx)     = p0;
        *(__nv_bfloat162*)(uh + idx + 2) = p1;
        __nv_bfloat162 q0, q1;
        q0.x = __float2bfloat16(v.x - __bfloat162float(h0));
        q0.y = __float2bfloat16(v.y - __bfloat162float(h1));
        q1.x = __float2bfloat16(v.z - __bfloat162float(h2));
        q1.y = __float2bfloat16(v.w - __bfloat162float(h3));
        *(__nv_bfloat162*)(ul + idx)     = q0;
        *(__nv_bfloat162*)(ul + idx + 2) = q1;
    }
}

// ---------------- fused HMMA kernel: one block per (h, 8 batches) -------------
// Warp layout: w = (mq | nh<<2): mq in 0..3 = 32-row band (MMA1) / 16-row tile
// (MMA2); nh in 0..1 = 16-column half of N=32.
extern __shared__ char smc[];
__global__ __launch_bounds__(256, 1) void fused_kernel() {
    int h   = blockIdx.y;
    int b0  = blockIdx.x * 8;
    int tid = threadIdx.x;
    int w   = tid >> 5, lane = tid & 31;
    int mq  = w & 3, nh = w >> 2;

    uint32_t sb = smem_to_u32(smc);

    // ---- stage operators: W 36864 B + A2 55296 B
    {
        const float4* s = (const float4*)(gW + (size_t)h * 18432);
        float4* d = (float4*)(smc + oWH);
        for (int i = tid; i < 2304; i += 256) d[i] = s[i];
        s = (const float4*)(gA2 + (size_t)h * 27648);
        d = (float4*)(smc + oA2);
        for (int i = tid; i < 3456; i += 256) d[i] = s[i];
    }
    float2 aC = make_float2(0.f, 0.f);
    if (tid < 64) aC = d_AbC[h * 64 + tid];
    stage_u(smc, d_ut + ((size_t)b0 * H_ + h) * L_, 0, tid, 256);
    __syncthreads();

    uint32_t laneA = (uint32_t)(((lane & 15) * 72 + (lane >> 4) * 8) * 2);
    uint32_t laneB = (uint32_t)(((lane & 7) * 72 + ((lane >> 3) & 1) * 8) * 2);

    // ---- cache invariant A fragments in registers
    uint32_t w1H[2][4][4], w1L[2][4][4];     // MMA1: 2 m-tiles (band), 4 kt
    {
        uint32_t base = sb + oWH + (uint32_t)(mq * 32 * 144) + laneA;
        #pragma unroll
        for (int mt = 0; mt < 2; mt++)
            #pragma unroll
            for (int kt = 0; kt < 4; kt++) {
                ldm_x4(w1H[mt][kt], base + (uint32_t)(mt * 16 * 144 + kt * 32));
                ldm_x4(w1L[mt][kt], base + (uint32_t)(mt * 16 * 144 + kt * 32) + 18432);
            }
    }
    uint32_t a2H[3][4][4], a2L[3][4][4];     // MMA2: 3 segs, 4 kt (m-tile = mq)
    {
        #pragma unroll
        for (int sg = 0; sg < 3; sg++) {
            uint32_t base = sb + oA2 + (uint32_t)(sg * 18432 + mq * 16 * 144) + laneA;
            #pragma unroll
            for (int kt = 0; kt < 4; kt++) {
                ldm_x4(a2H[sg][kt], base + (uint32_t)(kt * 32));
                ldm_x4(a2L[sg][kt], base + (uint32_t)(kt * 32) + 9216);
            }
        }
    }

    float* sD1 = (float*)(smc + oD1);
    int gid = lane >> 2, tq = lane & 3;

    for (int it = 0; it < 8; it++) {
        int b = b0 + it, buf = it & 1;
        uint32_t uhB = sb + oU + buf * 9216 + laneB;
        uint32_t ulB = uhB + 4608;

        // ---- MMA1: D1[128,32] = Wstack @ u^T   (band mq, n-half nh)
        {
            float acc[2][2][4];
            #pragma unroll
            for (int mt = 0; mt < 2; mt++)
                #pragma unroll
                for (int nt = 0; nt < 2; nt++)
                    #pragma unroll
                    for (int i = 0; i < 4; i++) acc[mt][nt][i] = 0.f;
            #pragma unroll
            for (int kt = 0; kt < 4; kt++) {
                uint32_t ko = kt * 32;
                uint32_t bh[2][2], bl[2][2];
                #pragma unroll
                for (int nt = 0; nt < 2; nt++) {
                    uint32_t bo = (uint32_t)((nh * 2 + nt) * 1152) + ko;
                    ldm_x2(bh[nt], uhB + bo);
                    ldm_x2(bl[nt], ulB + bo);
                }
                #pragma unroll
                for (int mt = 0; mt < 2; mt++)
                    #pragma unroll
                    for (int nt = 0; nt < 2; nt++) {
                        mma16816(acc[mt][nt], w1H[mt][kt], bh[nt]);
                        mma16816(acc[mt][nt], w1H[mt][kt], bl[nt]);
                        mma16816(acc[mt][nt], w1L[mt][kt], bh[nt]);
                    }
            }
            #pragma unroll
            for (int mt = 0; mt < 2; mt++)
                #pragma unroll
                for (int nt = 0; nt < 2; nt++) {
                    int c0 = nh * 16 + nt * 8 + tq * 2;
                    int r0 = mq * 32 + mt * 16 + gid;
                    sD1[r0 * 33 + c0]           = acc[mt][nt][0];
                    sD1[r0 * 33 + c0 + 1]       = acc[mt][nt][1];
                    sD1[(r0 + 8) * 33 + c0]     = acc[mt][nt][2];
                    sD1[(r0 + 8) * 33 + c0 + 1] = acc[mt][nt][3];
                }
        }
        __syncthreads();

        // ---- scan (warps 0,1) emit X tiles; warps 2-7 stage next u
        if (tid < 64) {
            __nv_bfloat16* xrH = (__nv_bfloat16*)(smc + oX);
            __nv_bfloat16* xrL = xrH + 2304;
            __nv_bfloat16* xiH = xrH + 4608;
            __nv_bfloat16* xiL = xrH + 6912;
            float xr = 0.f, xi = 0.f;
            #pragma unroll 4
            for (int c = 0; c < 32; c++) {
                float gr = sD1[tid * 33 + c];
                float gi = sD1[(64 + tid) * 33 + c];
                int idx = c * 72 + tid;
                __nv_bfloat16 hr = __float2bfloat16(xr);
                xrH[idx] = hr;
                xrL[idx] = __float2bfloat16(xr - __bfloat162float(hr));
                __nv_bfloat16 hi = __float2bfloat16(xi);
                xiH[idx] = hi;
                xiL[idx] = __float2bfloat16(xi - __bfloat162float(hi));
                float nx = aC.x * xr - aC.y * xi + gr;
                xi = aC.x * xi + aC.y * xr + gi;
                xr = nx;
            }
        } else if (it + 1 < 8) {
            stage_u(smc, d_ut + ((size_t)(b + 1) * H_ + h) * L_, buf ^ 1, tid - 64, 192);
        }
        __syncthreads();

        // ---- MMA2: D2[64,32] = A2[64,192] @ [xr|xi|u]^T  (m-tile mq, n-half nh)
        {
            float acc[2][4];
            #pragma unroll
            for (int nt = 0; nt < 2; nt++)
                #pragma unroll
                for (int i = 0; i < 4; i++) acc[nt][i] = 0.f;
            #pragma unroll
            for (int sg = 0; sg < 3; sg++) {
                uint32_t bHB = (sg == 2) ? uhB : (sb + oX + (uint32_t)(sg * 9216) + laneB);
                uint32_t bLB = bHB + 4608;
                #pragma unroll
                for (int kt = 0; kt < 4; kt++) {
                    uint32_t ko = kt * 32;
                    uint32_t bh[2][2], bl[2][2];
                    #pragma unroll
                    for (int nt = 0; nt < 2; nt++) {
                        uint32_t bo = (uint32_t)((nh * 2 + nt) * 1152) + ko;
                        ldm_x2(bh[nt], bHB + bo);
                        ldm_x2(bl[nt], bLB + bo);
                    }
                    #pragma unroll
                    for (int nt = 0; nt < 2; nt++) {
                        mma16816(acc[nt], a2H[sg][kt], bh[nt]);
                        mma16816(acc[nt], a2H[sg][kt], bl[nt]);
                        mma16816(acc[nt], a2L[sg][kt], bh[nt]);
                    }
                }
            }
            #pragma unroll
            for (int nt = 0; nt < 2; nt++) {
                int c0 = nh * 16 + nt * 8 + tq * 2;
                int i0 = mq * 16 + gid;
                sD1[i0 * 33 + c0]           = acc[nt][0];
                sD1[i0 * 33 + c0 + 1]       = acc[nt][1];
                sD1[(i0 + 8) * 33 + c0]     = acc[nt][2];
                sD1[(i0 + 8) * 33 + c0 + 1] = acc[nt][3];
            }
        }
        __syncthreads();

        // ---- coalesced store: y[l = c*64+i] = D2[i][c]
        {
            float* yp = d_yt + ((size_t)b * H_ + h) * L_;
            #pragma unroll
            for (int rep = 0; rep < 8; rep++) {
                int idx = rep * 256 + tid;
                yp[idx] = sD1[(idx & 63) * 33 + (idx >> 6)];
            }
        }
        __syncthreads();
    }
}

// ---------------- launch --------------------------------------------------------
extern "C" void kernel_launch(void* const* d_in, const int* in_sizes, int n_in,
                              void* d_out, int out_size) {
    const float* u     = (const float*)d_in[0];
    const float* Lr    = (const float*)d_in[1];
    const float* Li    = (const float*)d_in[2];
    const float* Br    = (const float*)d_in[3];
    const float* Bi    = (const float*)d_in[4];
    const float* Cr    = (const float*)d_in[5];
    const float* Ci    = (const float*)d_in[6];
    const float* logdt = (const float*)d_in[7];
    const float* D     = (const float*)d_in[8];
    float* out = (float*)d_out;

    float* ut_ptr; cudaGetSymbolAddress((void**)&ut_ptr, d_ut);
    float* yt_ptr; cudaGetSymbolAddress((void**)&yt_ptr, d_yt);

    cudaFuncSetAttribute(fused_kernel, cudaFuncAttributeMaxDynamicSharedMemorySize, SMEM_TOTAL);

    precompute_kernel<<<H_, N_>>>(Lr, Li, Br, Bi, Cr, Ci, logdt, D);
    transpose_BLH_to_BHL<<<dim3(H_ / 32, L_ / 32, B_), dim3(32, 8)>>>(u, ut_ptr);
    fused_kernel<<<dim3(2, H_), 256, SMEM_TOTAL>>>();
    transpose_BHL_to_BLH<<<dim3(L_ / 32, H_ / 32, B_), dim3(32, 8)>>>(yt_ptr, out);
}

// round 8
// speedup vs baseline: 4.6031x; 1.0921x over previous
#include <cuda_runtime.h>
#include <cuda_bf16.h>
#include <cstdint>

#define B_   16
#define L_   2048
#define H_   512
#define N_   64

// ---------------- fused-kernel dynamic smem layout (byte offsets) ------------
#define oWH  0          // W hi [128][72] bf16 = 18432 B
#define oWL  18432      // W lo
#define oA2  36864      // A2: seg{0,1,2} x {hi,lo}, each [64][72] bf16 = 9216 B
#define oU   92160      // u tiles: 2 bufs x (hi [32][72] + lo [32][72]) = 2 x 9216
#define oX   110592     // X tiles: xrH, xrL, xiH, xiL each [32][72] = 4 x 4608
#define oD1  129024     // fp32 exchange [128][33] = 16896 B (reused as 2x D2 [64][33])
#define oGS  145920     // scan group sums/prefixes: 4 arrays [64][9] fp32 = 9216 B
#define SMEM_TOTAL 155136

// ---------------- scratch (__device__ globals) --------------------------------
__device__ __align__(16) __nv_bfloat16 gW  [H_ * 18432];   // per h: WH 9216 | WL 9216
__device__ __align__(16) __nv_bfloat16 gA2 [H_ * 27648];   // per h: A0H A0L A1H A1L A2H A2L
__device__ __align__(16) float2 d_AbC[H_ * N_];             // Ab^C
__device__ __align__(16) float  d_ut [B_ * H_ * L_];        // u transposed (B,H,L)
__device__ __align__(16) float  d_yt [B_ * H_ * L_];        // y transposed (B,H,L)

__device__ __forceinline__ float2 cmul(float2 a, float2 b) {
    return make_float2(a.x * b.x - a.y * b.y, a.x * b.y + a.y * b.x);
}

// ---------------- PTX helpers (compute_80+; valid on plain sm_103) -----------
__device__ __forceinline__ uint32_t smem_to_u32(const void* p) {
    uint32_t a;
    asm("{ .reg .u64 t; cvta.to.shared.u64 t, %1; cvt.u32.u64 %0, t; }" : "=r"(a) : "l"(p));
    return a;
}
__device__ __forceinline__ void ldm_x4(uint32_t* r, uint32_t addr) {
    asm volatile("ldmatrix.sync.aligned.m8n8.x4.shared.b16 {%0,%1,%2,%3}, [%4];"
                 : "=r"(r[0]), "=r"(r[1]), "=r"(r[2]), "=r"(r[3]) : "r"(addr));
}
__device__ __forceinline__ void ldm_x2(uint32_t* r, uint32_t addr) {
    asm volatile("ldmatrix.sync.aligned.m8n8.x2.shared.b16 {%0,%1}, [%2];"
                 : "=r"(r[0]), "=r"(r[1]) : "r"(addr));
}
__device__ __forceinline__ void mma16816(float* d, const uint32_t* a, const uint32_t* b) {
    asm volatile("mma.sync.aligned.m16n8k16.row.col.f32.bf16.bf16.f32 "
                 "{%0,%1,%2,%3}, {%4,%5,%6,%7}, {%8,%9}, {%0,%1,%2,%3};"
                 : "+f"(d[0]), "+f"(d[1]), "+f"(d[2]), "+f"(d[3])
                 : "r"(a[0]), "r"(a[1]), "r"(a[2]), "r"(a[3]), "r"(b[0]), "r"(b[1]));
}

// split fp32 into bf16 hi/lo
__device__ __forceinline__ void put2(__nv_bfloat16* th, __nv_bfloat16* tl, int idx, float v) {
    __nv_bfloat16 hv = __float2bfloat16(v);
    th[idx] = hv;
    tl[idx] = __float2bfloat16(v - __bfloat162float(hv));
}

// ---------------- precompute: discretization + padded bf16x2 operators --------
__global__ void precompute_kernel(const float* __restrict__ Lr,
                                  const float* __restrict__ Li,
                                  const float* __restrict__ Br,
                                  const float* __restrict__ Bi,
                                  const float* __restrict__ Cr,
                                  const float* __restrict__ Ci,
                                  const float* __restrict__ logdt,
                                  const float* __restrict__ Din) {
    int h = blockIdx.x;
    int n = threadIdx.x;             // 64 threads
    int lane = n & 31, wid = n >> 5;

    float dt  = expf(logdt[h]);
    float lr  = Lr[n], li = Li[n];
    float er = expf(dt * lr);
    float s, c;
    sincosf(dt * li, &s, &c);
    float2 Ab = make_float2(er * c, er * s);

    float dr = lr + 1e-8f, di = li;
    float inv = 1.0f / (dr * dr + di * di);
    float2 Am1 = make_float2(Ab.x - 1.0f, Ab.y);
    float2 Bc  = make_float2(Br[h * N_ + n], Bi[h * N_ + n]);
    float2 num = cmul(Bc, Am1);
    float2 Bb  = make_float2((num.x * dr + num.y * di) * inv,
                             (num.y * dr - num.x * di) * inv);
    float2 Cc  = make_float2(Cr[h * N_ + n], Ci[h * N_ + n]);
    float2 CB  = cmul(Cc, Bb);

    __shared__ float sKpart[64][2];
    __shared__ float sKd[64];

    __nv_bfloat16* WH  = gW + (size_t)h * 18432;
    __nv_bfloat16* WL  = WH + 9216;
    __nv_bfloat16* A0H = gA2 + (size_t)h * 27648;
    __nv_bfloat16* A0L = A0H + 4608;
    __nv_bfloat16* A1H = A0H + 9216;
    __nv_bfloat16* A1L = A0H + 13824;
    __nv_bfloat16* A2H = A0H + 18432;
    __nv_bfloat16* A2L = A0H + 23040;

    float2 p = make_float2(1.0f, 0.0f);              // Ab^e
    for (int e = 0; e < 64; e++) {
        float2 w = cmul(p, Bb);                      // = Ab^{63-j} Bb at j = 63-e
        int j = 63 - e;
        put2(WH, WL, n * 72 + j, w.x);               // rows 0..63 : real
        put2(WH, WL, (64 + n) * 72 + j, w.y);        // rows 64..127 : imag
        float kv = CB.x * p.x - CB.y * p.y;          // K[e] partial (this n)
        #pragma unroll
        for (int off = 16; off; off >>= 1) kv += __shfl_xor_sync(0xffffffffu, kv, off);
        if (lane == 0) sKpart[e][wid] = kv;
        p = cmul(p, Ab);                             // Ab^{e+1}
        float2 m = cmul(Cc, p);                      // M[i=e][n]
        put2(A0H, A0L, e * 72 + n, m.x);             // seg0: Mr
        put2(A1H, A1L, e * 72 + n, -m.y);            // seg1: -Mi
    }
    d_AbC[h * N_ + n] = p;                           // Ab^C
    __syncthreads();
    sKd[n] = sKpart[n][0] + sKpart[n][1];            // K[d = n]
    __syncthreads();

    float Dh = Din[h];
    for (int i = 0; i < 64; i++) {                   // seg2: Toeplitz + D on diagonal
        float v = (i > n) ? sKd[i - n] : (i == n ? sKd[0] + Dh : 0.0f);
        put2(A2H, A2L, i * 72 + n, v);
    }
}

// ---------------- transposes ---------------------------------------------------
__global__ void transpose_BLH_to_BHL(const float* __restrict__ in, float* __restrict__ out) {
    __shared__ float tile[32][33];
    int b = blockIdx.z;
    int h0 = blockIdx.x * 32, l0 = blockIdx.y * 32;
    int tx = threadIdx.x, ty = threadIdx.y;   // (32, 8)
    #pragma unroll
    for (int k = 0; k < 4; k++) {
        int l = l0 + ty + k * 8;
        tile[ty + k * 8][tx] = in[((size_t)b * L_ + l) * H_ + h0 + tx];
    }
    __syncthreads();
    #pragma unroll
    for (int k = 0; k < 4; k++) {
        int h = h0 + ty + k * 8;
        out[((size_t)b * H_ + h) * L_ + l0 + tx] = tile[tx][ty + k * 8];
    }
}

__global__ void transpose_BHL_to_BLH(const float* __restrict__ in, float* __restrict__ out) {
    __shared__ float tile[32][33];
    int b = blockIdx.z;
    int l0 = blockIdx.x * 32, h0 = blockIdx.y * 32;
    int tx = threadIdx.x, ty = threadIdx.y;
    #pragma unroll
    for (int k = 0; k < 4; k++) {
        int h = h0 + ty + k * 8;
        tile[ty + k * 8][tx] = in[((size_t)b * H_ + h) * L_ + l0 + tx];
    }
    __syncthreads();
    #pragma unroll
    for (int k = 0; k < 4; k++) {
        int l = l0 + ty + k * 8;
        out[((size_t)b * L_ + l) * H_ + h0 + tx] = tile[tx][ty + k * 8];
    }
}

// ---------------- u staging: fp32 -> bf16 hi/lo padded tile -------------------
__device__ __forceinline__ void stage_u(char* smc, const float* __restrict__ up,
                                        int buf, int tstart, int tstep) {
    const float4* s = (const float4*)up;
    __nv_bfloat16* uh = (__nv_bfloat16*)(smc + oU + buf * 9216);
    __nv_bfloat16* ul = uh + 2304;
    for (int f = tstart; f < 512; f += tstep) {
        float4 v = s[f];
        int idx = (f >> 4) * 72 + (f & 15) * 4;      // [chunk][time]
        __nv_bfloat16 h0 = __float2bfloat16(v.x), h1 = __float2bfloat16(v.y);
        __nv_bfloat16 h2 = __float2bfloat16(v.z), h3 = __float2bfloat16(v.w);
        __nv_bfloat162 p0; p0.x = h0; p0.y = h1;
        __nv_bfloat162 p1; p1.x = h2; p1.y = h3;
        *(__nv_bfloat162*)(uh + idx)     = p0;
        *(__nv_bfloat162*)(uh + idx + 2) = p1;
        __nv_bfloat162 q0, q1;
        q0.x = __float2bfloat16(v.x - __bfloat162float(h0));
        q0.y = __float2bfloat16(v.y - __bfloat162float(h1));
        q1.x = __float2bfloat16(v.z - __bfloat162float(h2));
        q1.y = __float2bfloat16(v.w - __bfloat162float(h3));
        *(__nv_bfloat162*)(ul + idx)     = q0;
        *(__nv_bfloat162*)(ul + idx + 2) = q1;
    }
}

// ---------------- fused HMMA kernel: 512 threads, one block per (h, 8b) -------
extern __shared__ char smc[];
__global__ __launch_bounds__(512, 1) void fused_kernel() {
    int h   = blockIdx.y;
    int b0  = blockIdx.x * 8;
    int tid = threadIdx.x;
    int w   = tid >> 5, lane = tid & 31;

    uint32_t sb = smem_to_u32(smc);

    // ---- stage operators: W 36864 B + A2 55296 B
    {
        const float4* s = (const float4*)(gW + (size_t)h * 18432);
        float4* d = (float4*)(smc + oWH);
        for (int i = tid; i < 2304; i += 512) d[i] = s[i];
        s = (const float4*)(gA2 + (size_t)h * 27648);
        d = (float4*)(smc + oA2);
        for (int i = tid; i < 3456; i += 512) d[i] = s[i];
    }
    stage_u(smc, d_ut + ((size_t)b0 * H_ + h) * L_, 0, tid, 512);

    // scan constants (per n = tid & 63)
    int sn = tid & 63, sq = tid >> 6;                // n, chunk-group (0..7)
    float2 a1 = d_AbC[h * 64 + sn];
    float2 a2c = cmul(a1, a1);
    float2 a3c = cmul(a2c, a1);
    float2 a4c = cmul(a2c, a2c);
    __syncthreads();

    uint32_t laneA = (uint32_t)(((lane & 15) * 72 + (lane >> 4) * 8) * 2);
    uint32_t laneB = (uint32_t)(((lane & 7) * 72 + ((lane >> 3) & 1) * 8) * 2);

    // MMA1 tiling: mq1 = m-tile (16 rows), nh1 = 16-col half
    int mq1 = w & 7, nh1 = w >> 3;
    uint32_t w1Hb = sb + oWH + (uint32_t)(mq1 * 16 * 144) + laneA;
    uint32_t w1Lb = w1Hb + 18432;

    // MMA2 tiling: mq2 = m-tile, nh2 = n-half, ng = k-half (6 chunks each)
    int mq2 = w & 3, nh2 = (w >> 2) & 1, ng = w >> 3;
    uint32_t a2H[6][4], a2L[6][4];       // cached A2 frags (48 regs)
    #pragma unroll
    for (int kcl = 0; kcl < 6; kcl++) {
        int kc = ng * 6 + kcl, sg = kc >> 2, kt = kc & 3;
        uint32_t base = sb + oA2 + (uint32_t)(sg * 18432 + mq2 * 16 * 144 + kt * 32) + laneA;
        ldm_x4(a2H[kcl], base);
        ldm_x4(a2L[kcl], base + 9216);
    }

    float* sD1  = (float*)(smc + oD1);
    float* sGSr = (float*)(smc + oGS);
    float* sGSi = sGSr + 576;
    float* sXPr = sGSr + 1152;
    float* sXPi = sGSr + 1728;
    int gid = lane >> 2, tq = lane & 3;

    for (int it = 0; it < 8; it++) {
        int b = b0 + it, buf = it & 1;
        uint32_t uhB = sb + oU + buf * 9216 + laneB;
        uint32_t ulB = uhB + 4608;

        // ---- MMA1: D1[128,32] = Wstack @ u^T   (m-tile mq1, n-half nh1)
        {
            float acc[2][4];
            #pragma unroll
            for (int nt = 0; nt < 2; nt++)
                #pragma unroll
                for (int i = 0; i < 4; i++) acc[nt][i] = 0.f;
            #pragma unroll
            for (int kt = 0; kt < 4; kt++) {
                uint32_t ko = kt * 32;
                uint32_t aH[4], aL[4];
                ldm_x4(aH, w1Hb + ko);
                ldm_x4(aL, w1Lb + ko);
                #pragma unroll
                for (int nt = 0; nt < 2; nt++) {
                    uint32_t bo = (uint32_t)((nh1 * 2 + nt) * 1152) + ko;
                    uint32_t bh[2], bl[2];
                    ldm_x2(bh, uhB + bo);
                    ldm_x2(bl, ulB + bo);
                    mma16816(acc[nt], aH, bh);
                    mma16816(acc[nt], aH, bl);
                    mma16816(acc[nt], aL, bh);
                }
            }
            #pragma unroll
            for (int nt = 0; nt < 2; nt++) {
                int c0 = nh1 * 16 + nt * 8 + tq * 2;
                int r0 = mq1 * 16 + gid;
                sD1[r0 * 33 + c0]           = acc[nt][0];
                sD1[r0 * 33 + c0 + 1]       = acc[nt][1];
                sD1[(r0 + 8) * 33 + c0]     = acc[nt][2];
                sD1[(r0 + 8) * 33 + c0 + 1] = acc[nt][3];
            }
        }
        __syncthreads();

        // ---- scan step A: local inclusive prefix over this thread's 4 chunks
        float hr0, hi0, hr1, hi1, hr2, hi2, hr3, hi3;
        {
            int cb = sq * 4;
            hr0 = sD1[sn * 33 + cb];
            hi0 = sD1[(64 + sn) * 33 + cb];
            float gr = sD1[sn * 33 + cb + 1], gi = sD1[(64 + sn) * 33 + cb + 1];
            hr1 = a1.x * hr0 - a1.y * hi0 + gr;
            hi1 = a1.x * hi0 + a1.y * hr0 + gi;
            gr = sD1[sn * 33 + cb + 2]; gi = sD1[(64 + sn) * 33 + cb + 2];
            hr2 = a1.x * hr1 - a1.y * hi1 + gr;
            hi2 = a1.x * hi1 + a1.y * hr1 + gi;
            gr = sD1[sn * 33 + cb + 3]; gi = sD1[(64 + sn) * 33 + cb + 3];
            hr3 = a1.x * hr2 - a1.y * hi2 + gr;
            hi3 = a1.x * hi2 + a1.y * hr2 + gi;
            sGSr[sn * 9 + sq] = hr3;
            sGSi[sn * 9 + sq] = hi3;
        }
        __syncthreads();

        // ---- scan step B: 64 threads scan 8 group sums; others stage next u
        if (tid < 64) {
            float Xr = 0.f, Xi = 0.f;
            #pragma unroll
            for (int q = 0; q < 8; q++) {
                sXPr[tid * 9 + q] = Xr;
                sXPi[tid * 9 + q] = Xi;
                float nr = a4c.x * Xr - a4c.y * Xi + sGSr[tid * 9 + q];
                Xi = a4c.x * Xi + a4c.y * Xr + sGSi[tid * 9 + q];
                Xr = nr;
            }
        } else if (it + 1 < 8) {
            stage_u(smc, d_ut + ((size_t)(b + 1) * H_ + h) * L_, buf ^ 1, tid - 64, 448);
        }
        __syncthreads();

        // ---- scan step C: correct + emit bf16 hi/lo X tiles (x_pre per chunk)
        {
            __nv_bfloat16* xrH = (__nv_bfloat16*)(smc + oX);
            __nv_bfloat16* xrL = xrH + 2304;
            __nv_bfloat16* xiH = xrH + 4608;
            __nv_bfloat16* xiL = xrH + 6912;
            float X0r = sXPr[sn * 9 + sq], X0i = sXPi[sn * 9 + sq];
            int cb = sq * 4;
            float pr, pi;
            int idx = cb * 72 + sn;
            put2(xrH, xrL, idx, X0r);
            put2(xiH, xiL, idx, X0i);
            pr = a1.x * X0r - a1.y * X0i + hr0;
            pi = a1.x * X0i + a1.y * X0r + hi0;
            idx += 72;
            put2(xrH, xrL, idx, pr);
            put2(xiH, xiL, idx, pi);
            pr = a2c.x * X0r - a2c.y * X0i + hr1;
            pi = a2c.x * X0i + a2c.y * X0r + hi1;
            idx += 72;
            put2(xrH, xrL, idx, pr);
            put2(xiH, xiL, idx, pi);
            pr = a3c.x * X0r - a3c.y * X0i + hr2;
            pi = a3c.x * X0i + a3c.y * X0r + hi2;
            idx += 72;
            put2(xrH, xrL, idx, pr);
            put2(xiH, xiL, idx, pi);
        }
        __syncthreads();

        // ---- MMA2 (k-split): partial D2 = A2[kchunks ng] @ [xr|xi|u]^T
        {
            float acc[2][4];
            #pragma unroll
            for (int nt = 0; nt < 2; nt++)
                #pragma unroll
                for (int i = 0; i < 4; i++) acc[nt][i] = 0.f;
            #pragma unroll
            for (int kcl = 0; kcl < 6; kcl++) {
                int kc = ng * 6 + kcl, sg = kc >> 2, kt = kc & 3;
                uint32_t ko = kt * 32;
                uint32_t bHB = (sg == 2) ? (uhB + ko)
                                         : (sb + oX + (uint32_t)(sg * 9216) + laneB + ko);
                uint32_t bLB = bHB + 4608;
                #pragma unroll
                for (int nt = 0; nt < 2; nt++) {
                    uint32_t bo = (uint32_t)((nh2 * 2 + nt) * 1152);
                    uint32_t bh[2], bl[2];
                    ldm_x2(bh, bHB + bo);
                    ldm_x2(bl, bLB + bo);
                    mma16816(acc[nt], a2H[kcl], bh);
                    mma16816(acc[nt], a2H[kcl], bl);
                    mma16816(acc[nt], a2L[kcl], bh);
                }
            }
            float* sD2 = sD1 + ng * 2112;            // two [64][33] partial buffers
            #pragma unroll
            for (int nt = 0; nt < 2; nt++) {
                int c0 = nh2 * 16 + nt * 8 + tq * 2;
                int i0 = mq2 * 16 + gid;
                sD2[i0 * 33 + c0]           = acc[nt][0];
                sD2[i0 * 33 + c0 + 1]       = acc[nt][1];
                sD2[(i0 + 8) * 33 + c0]     = acc[nt][2];
                sD2[(i0 + 8) * 33 + c0 + 1] = acc[nt][3];
            }
        }
        __syncthreads();

        // ---- store: y[l = c*64+i] = D2a[i][c] + D2b[i][c]
        {
            float* yp = d_yt + ((size_t)b * H_ + h) * L_;
            #pragma unroll
            for (int rep = 0; rep < 4; rep++) {
                int idx = rep * 512 + tid;
                int i = idx & 63, c = idx >> 6;
                yp[idx] = sD1[i * 33 + c] + sD1[2112 + i * 33 + c];
            }
        }
        __syncthreads();
    }
}

// ---------------- launch --------------------------------------------------------
extern "C" void kernel_launch(void* const* d_in, const int* in_sizes, int n_in,
                              void* d_out, int out_size) {
    const float* u     = (const float*)d_in[0];
    const float* Lr    = (const float*)d_in[1];
    const float* Li    = (const float*)d_in[2];
    const float* Br    = (const float*)d_in[3];
    const float* Bi    = (const float*)d_in[4];
    const float* Cr    = (const float*)d_in[5];
    const float* Ci    = (const float*)d_in[6];
    const float* logdt = (const float*)d_in[7];
    const float* D     = (const float*)d_in[8];
    float* out = (float*)d_out;

    float* ut_ptr; cudaGetSymbolAddress((void**)&ut_ptr, d_ut);
    float* yt_ptr; cudaGetSymbolAddress((void**)&yt_ptr, d_yt);

    cudaFuncSetAttribute(fused_kernel, cudaFuncAttributeMaxDynamicSharedMemorySize, SMEM_TOTAL);

    precompute_kernel<<<H_, N_>>>(Lr, Li, Br, Bi, Cr, Ci, logdt, D);
    transpose_BLH_to_BHL<<<dim3(H_ / 32, L_ / 32, B_), dim3(32, 8)>>>(u, ut_ptr);
    fused_kernel<<<dim3(2, H_), 512, SMEM_TOTAL>>>();
    transpose_BHL_to_BLH<<<dim3(L_ / 32, H_ / 32, B_), dim3(32, 8)>>>(yt_ptr, out);
}